// round 5
// baseline (speedup 1.0000x reference)
#include <cuda_runtime.h>
#include <cuda_fp16.h>
#include <cstdint>

// Problem dims (fixed by the dataset)
#define MDIM 8192
#define KDIM 4096
#define NDIM 4096

// ---------------- device scratch (sanctioned: __device__ globals) ----------
__device__ __half g_weffh[(size_t)NDIM * KDIM];  // 32 MB: dequant + lora folded, fp16
__device__ __half g_xh[(size_t)MDIM * KDIM];     // 64 MB: x rounded to fp16 (RN)

// ---------------- helpers ---------------------------------------------------
__device__ __forceinline__ uint32_t smem_u32(const void* p) {
    uint32_t a;
    asm("{ .reg .u64 t; cvta.to.shared.u64 t, %1; cvt.u32.u64 %0, t; }" : "=r"(a) : "l"(p));
    return a;
}
__device__ __forceinline__ void cp16(uint32_t dst, const void* src) {
    asm volatile("cp.async.cg.shared.global [%0], [%1], 16;" :: "r"(dst), "l"(src));
}
__device__ __forceinline__ void cp_commit() {
    asm volatile("cp.async.commit_group;" ::: "memory");
}
template <int N>
__device__ __forceinline__ void cp_wait() {
    asm volatile("cp.async.wait_group %0;" :: "n"(N) : "memory");
}
__device__ __forceinline__ void ldsm4(uint32_t r[4], uint32_t addr) {
    asm volatile("ldmatrix.sync.aligned.m8n8.x4.shared.b16 {%0,%1,%2,%3}, [%4];"
                 : "=r"(r[0]), "=r"(r[1]), "=r"(r[2]), "=r"(r[3]) : "r"(addr));
}
__device__ __forceinline__ void mma16(float c[4], const uint32_t a[4],
                                      uint32_t b0, uint32_t b1) {
    asm volatile("mma.sync.aligned.m16n8k16.row.col.f32.f16.f16.f32 "
                 "{%0,%1,%2,%3}, {%4,%5,%6,%7}, {%8,%9}, {%0,%1,%2,%3};"
                 : "+f"(c[0]), "+f"(c[1]), "+f"(c[2]), "+f"(c[3])
                 : "r"(a[0]), "r"(a[1]), "r"(a[2]), "r"(a[3]), "r"(b0), "r"(b1));
}

// ---------------- fused prologue: round x AND build W_eff ------------------
// blocks [0, RX_BLOCKS): round x to fp16
// blocks [RX_BLOCKS, RX_BLOCKS + PW_BLOCKS): dequant + lora -> g_weffh
#define RX_BLOCKS ((MDIM * KDIM) / 1024)          // 32768, 256 thr x float4
#define PW_BX (KDIM / 512)                        // 8
#define PW_BY (NDIM / 16)                         // 256
#define PW_BLOCKS (PW_BX * PW_BY)                 // 2048

__global__ void __launch_bounds__(256) prologue_kernel(
    const float4* __restrict__ x,
    const int* __restrict__ qweight, const float* __restrict__ wscales,
    const float* __restrict__ proj_down, const float* __restrict__ proj_up,
    const float* __restrict__ wtscale)
{
    const int tid = threadIdx.x;
    if (blockIdx.x < RX_BLOCKS) {
        // ---- round x to fp16 ----
        int i = blockIdx.x * 256 + tid;
        float4 v = x[i];
        __half2* gx = reinterpret_cast<__half2*>(g_xh);
        gx[2 * i + 0] = __floats2half2_rn(v.x, v.y);
        gx[2 * i + 1] = __floats2half2_rn(v.z, v.w);
        return;
    }
    // ---- W_eff = dequant(q,scale) + wtscale * up@down ----
    const int pbid = blockIdx.x - RX_BLOCKS;
    const int bx = pbid & (PW_BX - 1);
    const int by = pbid / PW_BX;

    __shared__ float up_s[16 * 32];
    const int n0 = by * 16;
    #pragma unroll
    for (int j = tid; j < 512; j += 256) {
        int n = j >> 5, r = j & 31;
        up_s[j] = proj_up[(size_t)(n0 + n) * 32 + r];
    }
    __syncthreads();
    const float wt = wtscale[0];
    const int k2 = bx * 256 + tid;   // pair index; k = 2*k2, 2*k2+1

    float ae[16], ao[16];
    #pragma unroll
    for (int n = 0; n < 16; n++) { ae[n] = 0.f; ao[n] = 0.f; }
    #pragma unroll 4
    for (int r = 0; r < 32; r++) {
        float2 d2 = *reinterpret_cast<const float2*>(proj_down + (size_t)r * KDIM + 2 * k2);
        #pragma unroll
        for (int n = 0; n < 16; n++) {
            float u = up_s[n * 32 + r];
            ae[n] = fmaf(u, d2.x, ae[n]);
            ao[n] = fmaf(u, d2.y, ao[n]);
        }
    }
    const int g = k2 >> 5;  // (2*k2)/64
    #pragma unroll
    for (int n = 0; n < 16; n++) {
        int q = qweight[(size_t)(n0 + n) * (KDIM / 2) + k2];
        float s = wscales[(size_t)g * NDIM + (n0 + n)];
        float we = fmaf((float)((q & 15) - 8), s, wt * ae[n]);
        float wo = fmaf((float)(((q >> 4) & 15) - 8), s, wt * ao[n]);
        *reinterpret_cast<__half2*>(g_weffh + (size_t)(n0 + n) * KDIM + 2 * k2) =
            __floats2half2_rn(we, wo);
    }
}

// ---------------- GEMM: out = g_xh @ g_weffh^T + bias (fp32 accumulate) ----
// Fragment double-buffering + fine-grained LDSM/MMA interleave:
// per k-step: LDSM A(next) -> 16 MMA -> LDSM B(next) -> 16 MMA.
#define BM 128
#define BN 128
#define BK 64
#define STAGES 3
#define KTILES (KDIM / BK)            // 64
#define A_BYTES (BM * BK * 2)         // 16384
#define STAGE_BYTES (2 * A_BYTES)     // 32768 (A then B)
#define SMEM_TOTAL (STAGES * STAGE_BYTES)

__global__ void __launch_bounds__(128, 2) gemm_fp16_kernel(
    const float* __restrict__ bias, float* __restrict__ out)
{
    extern __shared__ char smem_raw[];
    const uint32_t sbase = smem_u32(smem_raw);

    const int tid  = threadIdx.x;
    const int lane = tid & 31;
    const int warp = tid >> 5;
    const int wm = warp & 1;          // 2 warps in m -> warp tile 64 rows
    const int wn = warp >> 1;         // 2 warps in n -> warp tile 64 cols
    const int m0 = blockIdx.y * BM;
    const int n0 = blockIdx.x * BN;

    // ---- cp.async source/dest (thread t owns A row t and B row t) ----
    const char* srcA = (const char*)(g_xh    + (size_t)(m0 + tid) * KDIM);
    const char* srcB = (const char*)(g_weffh + (size_t)(n0 + tid) * KDIM);
    const uint32_t dstRow = sbase + (uint32_t)tid * 128;  // within-stage row base
    const int rsw = tid & 7;                               // store swizzle

    // ---- ldmatrix per-lane addressing ----
    const int lr = lane & 7;
    const int g1 = (lane >> 3) & 1;
    const int g2 = lane >> 4;
    const uint32_t aOff = (uint32_t)(wm * 64 + lr + (g1 << 3)) * 128;
    const uint32_t bOff = (uint32_t)(wn * 64 + lr + (g2 << 3)) * 128;

    float acc[4][8][4];
    #pragma unroll
    for (int i = 0; i < 4; i++)
        #pragma unroll
        for (int j = 0; j < 8; j++)
            #pragma unroll
            for (int c = 0; c < 4; c++) acc[i][j][c] = 0.f;

    // ---- stage loader: 8 chunks x 16B per row = 64 halves (BK) ----
    auto load_stage = [&](int st, int kt) {
        uint32_t sa = dstRow + (uint32_t)st * STAGE_BYTES;
        const char* ga = srcA + (size_t)kt * (BK * 2);
        const char* gb = srcB + (size_t)kt * (BK * 2);
        #pragma unroll
        for (int c = 0; c < 8; c++) {
            uint32_t off = (uint32_t)((c ^ rsw) << 4);
            cp16(sa + off,           ga + c * 16);
            cp16(sa + A_BYTES + off, gb + c * 16);
        }
    };

    // fragment double buffers
    uint32_t fa[2][4][4], fb[2][4][4];

    auto ldsmA = [&](int buf, int st, int s) {
        const uint32_t aSt = sbase + (uint32_t)st * STAGE_BYTES + aOff;
        const uint32_t xA = (uint32_t)(((2 * s + g2) ^ lr) << 4);
        #pragma unroll
        for (int mt = 0; mt < 4; mt++) ldsm4(fa[buf][mt], aSt + mt * 2048 + xA);
    };
    auto ldsmB = [&](int buf, int st, int s) {
        const uint32_t bSt = sbase + (uint32_t)st * STAGE_BYTES + A_BYTES + bOff;
        const uint32_t xB = (uint32_t)(((2 * s + g1) ^ lr) << 4);
        #pragma unroll
        for (int p = 0; p < 4; p++) ldsm4(fb[buf][p], bSt + p * 2048 + xB);
    };

    // half = 0 -> n-pairs p=0,1 ; half = 1 -> p=2,3  (16 MMAs each)
    auto mma_half = [&](int buf, int half) {
        #pragma unroll
        for (int p = 2 * half; p < 2 * half + 2; p++) {
            #pragma unroll
            for (int mt = 0; mt < 4; mt++) {
                mma16(acc[mt][2 * p],     fa[buf][mt], fb[buf][p][0], fb[buf][p][1]);
                mma16(acc[mt][2 * p + 1], fa[buf][mt], fb[buf][p][2], fb[buf][p][3]);
            }
        }
    };

    // ---- prologue: prefetch 2 stages, then preload step-0 fragments ----
    load_stage(0, 0); cp_commit();
    load_stage(1, 1); cp_commit();
    cp_wait<1>();
    __syncthreads();
    ldsmA(0, 0, 0);
    ldsmB(0, 0, 0);

    int st = 0;
    for (int kt = 0; kt < KTILES; kt++) {
        // prefetch kt+2 into the stage consumed at kt-1
        if (kt + 2 < KTILES) {
            int st2 = st + 2; if (st2 >= STAGES) st2 -= STAGES;
            load_stage(st2, kt + 2);
        }
        cp_commit();

        int stn = st + 1; if (stn >= STAGES) stn = 0;

        #pragma unroll
        for (int s = 0; s < 4; s++) {
            const int cur = s & 1;
            const int nxt = cur ^ 1;
            if (s < 3) {
                ldsmA(nxt, st, s + 1);       // spread LSU ops through the
                mma_half(cur, 0);            // tensor stream; every fragment
                ldsmB(nxt, st, s + 1);       // gets >=16 MMA issues of slack
                mma_half(cur, 1);
            } else {
                mma_half(cur, 0);
                mma_half(cur, 1);            // last MMAs cover the barrier
                if (kt + 1 < KTILES) {
                    cp_wait<1>();
                    __syncthreads();
                    ldsmA(nxt, stn, 0);      // preload next tile's step 0
                    ldsmB(nxt, stn, 0);
                }
            }
        }
        st = stn;
    }

    // ---- epilogue: add bias, store float2 ----
    const int mrow = m0 + wm * 64 + (lane >> 2);
    const int ncol = n0 + wn * 64 + 2 * (lane & 3);
    float2 bv[8];
    #pragma unroll
    for (int nt = 0; nt < 8; nt++)
        bv[nt] = *reinterpret_cast<const float2*>(bias + ncol + nt * 8);

    #pragma unroll
    for (int mt = 0; mt < 4; mt++) {
        float* r0 = out + (size_t)(mrow + mt * 16) * NDIM + ncol;
        float* r1 = out + (size_t)(mrow + mt * 16 + 8) * NDIM + ncol;
        #pragma unroll
        for (int nt = 0; nt < 8; nt++) {
            float2 v0 = make_float2(acc[mt][nt][0] + bv[nt].x, acc[mt][nt][1] + bv[nt].y);
            float2 v1 = make_float2(acc[mt][nt][2] + bv[nt].x, acc[mt][nt][3] + bv[nt].y);
            *reinterpret_cast<float2*>(r0 + nt * 8) = v0;
            *reinterpret_cast<float2*>(r1 + nt * 8) = v1;
        }
    }
}

// ---------------- launch ----------------------------------------------------
extern "C" void kernel_launch(void* const* d_in, const int* in_sizes, int n_in,
                              void* d_out, int out_size) {
    const float* x    = (const float*)d_in[0];
    const int*   qw   = (const int*)d_in[1];
    const float* ws   = (const float*)d_in[2];
    const float* pd   = (const float*)d_in[3];
    const float* pu   = (const float*)d_in[4];
    const float* wt   = (const float*)d_in[5];
    const float* bias = (const float*)d_in[6];
    float* out = (float*)d_out;

    // fused: x->fp16 rounding + W_eff build (independent, one launch)
    prologue_kernel<<<RX_BLOCKS + PW_BLOCKS, 256>>>(
        (const float4*)x, qw, ws, pd, pu, wt);

    // main GEMM
    cudaFuncSetAttribute(gemm_fp16_kernel, cudaFuncAttributeMaxDynamicSharedMemorySize, SMEM_TOTAL);
    gemm_fp16_kernel<<<dim3(NDIM / BN, MDIM / BM), 128, SMEM_TOTAL>>>(bias, out);
}

// round 6
// speedup vs baseline: 1.0282x; 1.0282x over previous
#include <cuda_runtime.h>
#include <cuda_fp16.h>
#include <cstdint>

// Problem dims (fixed by the dataset)
#define MDIM 8192
#define KDIM 4096
#define NDIM 4096

// ---------------- device scratch (sanctioned: __device__ globals) ----------
__device__ __half g_weffh[(size_t)NDIM * KDIM];  // 32 MB: dequant + lora folded, fp16
__device__ __half g_xh[(size_t)MDIM * KDIM];     // 64 MB: x rounded to fp16 (RN)

// ---------------- helpers ---------------------------------------------------
__device__ __forceinline__ uint32_t smem_u32(const void* p) {
    uint32_t a;
    asm("{ .reg .u64 t; cvta.to.shared.u64 t, %1; cvt.u32.u64 %0, t; }" : "=r"(a) : "l"(p));
    return a;
}
__device__ __forceinline__ void cp16(uint32_t dst, const void* src) {
    asm volatile("cp.async.cg.shared.global [%0], [%1], 16;" :: "r"(dst), "l"(src));
}
__device__ __forceinline__ void cp_commit() {
    asm volatile("cp.async.commit_group;" ::: "memory");
}
template <int N>
__device__ __forceinline__ void cp_wait() {
    asm volatile("cp.async.wait_group %0;" :: "n"(N) : "memory");
}
__device__ __forceinline__ void ldsm4(uint32_t r[4], uint32_t addr) {
    asm volatile("ldmatrix.sync.aligned.m8n8.x4.shared.b16 {%0,%1,%2,%3}, [%4];"
                 : "=r"(r[0]), "=r"(r[1]), "=r"(r[2]), "=r"(r[3]) : "r"(addr));
}
__device__ __forceinline__ void mma16(float c[4], const uint32_t a[4],
                                      uint32_t b0, uint32_t b1) {
    asm volatile("mma.sync.aligned.m16n8k16.row.col.f32.f16.f16.f32 "
                 "{%0,%1,%2,%3}, {%4,%5,%6,%7}, {%8,%9}, {%0,%1,%2,%3};"
                 : "+f"(c[0]), "+f"(c[1]), "+f"(c[2]), "+f"(c[3])
                 : "r"(a[0]), "r"(a[1]), "r"(a[2]), "r"(a[3]), "r"(b0), "r"(b1));
}

// ---------------- fused prologue: round x AND build W_eff ------------------
#define RX_BLOCKS ((MDIM * KDIM) / 1024)          // 32768, 256 thr x float4
#define PW_BX (KDIM / 512)                        // 8
#define PW_BY (NDIM / 16)                         // 256
#define PW_BLOCKS (PW_BX * PW_BY)                 // 2048

__global__ void __launch_bounds__(256) prologue_kernel(
    const float4* __restrict__ x,
    const int* __restrict__ qweight, const float* __restrict__ wscales,
    const float* __restrict__ proj_down, const float* __restrict__ proj_up,
    const float* __restrict__ wtscale)
{
    const int tid = threadIdx.x;
    if (blockIdx.x < RX_BLOCKS) {
        // ---- round x to fp16 ----
        int i = blockIdx.x * 256 + tid;
        float4 v = x[i];
        __half2* gx = reinterpret_cast<__half2*>(g_xh);
        gx[2 * i + 0] = __floats2half2_rn(v.x, v.y);
        gx[2 * i + 1] = __floats2half2_rn(v.z, v.w);
        return;
    }
    // ---- W_eff = dequant(q,scale) + wtscale * up@down ----
    const int pbid = blockIdx.x - RX_BLOCKS;
    const int bx = pbid & (PW_BX - 1);
    const int by = pbid / PW_BX;

    __shared__ float up_s[16 * 32];
    const int n0 = by * 16;
    #pragma unroll
    for (int j = tid; j < 512; j += 256) {
        int n = j >> 5, r = j & 31;
        up_s[j] = proj_up[(size_t)(n0 + n) * 32 + r];
    }
    __syncthreads();
    const float wt = wtscale[0];
    const int k2 = bx * 256 + tid;   // pair index; k = 2*k2, 2*k2+1

    float ae[16], ao[16];
    #pragma unroll
    for (int n = 0; n < 16; n++) { ae[n] = 0.f; ao[n] = 0.f; }
    #pragma unroll 4
    for (int r = 0; r < 32; r++) {
        float2 d2 = *reinterpret_cast<const float2*>(proj_down + (size_t)r * KDIM + 2 * k2);
        #pragma unroll
        for (int n = 0; n < 16; n++) {
            float u = up_s[n * 32 + r];
            ae[n] = fmaf(u, d2.x, ae[n]);
            ao[n] = fmaf(u, d2.y, ao[n]);
        }
    }
    const int g = k2 >> 5;  // (2*k2)/64
    #pragma unroll
    for (int n = 0; n < 16; n++) {
        int q = qweight[(size_t)(n0 + n) * (KDIM / 2) + k2];
        float s = wscales[(size_t)g * NDIM + (n0 + n)];
        float we = fmaf((float)((q & 15) - 8), s, wt * ae[n]);
        float wo = fmaf((float)(((q >> 4) & 15) - 8), s, wt * ao[n]);
        *reinterpret_cast<__half2*>(g_weffh + (size_t)(n0 + n) * KDIM + 2 * k2) =
            __floats2half2_rn(we, wo);
    }
}

// ---------------- GEMM: out = g_xh @ g_weffh^T + bias (fp32 accumulate) ----
// 256 threads / 8 warps per CTA, warp tile 32x64, 2 CTAs/SM => 16 warps/SM
// (4 per SMSP). Latency hiding via TLP; single-buffered fragments keep
// registers under 128 so both CTAs stay resident.
#define BM 128
#define BN 128
#define BK 64
#define STAGES 3
#define KTILES (KDIM / BK)            // 64
#define A_BYTES (BM * BK * 2)         // 16384
#define STAGE_BYTES (2 * A_BYTES)     // 32768 (A then B)
#define SMEM_TOTAL (STAGES * STAGE_BYTES)

__global__ void __launch_bounds__(256, 2) gemm_fp16_kernel(
    const float* __restrict__ bias, float* __restrict__ out)
{
    extern __shared__ char smem_raw[];
    const uint32_t sbase = smem_u32(smem_raw);

    const int tid  = threadIdx.x;
    const int lane = tid & 31;
    const int warp = tid >> 5;
    const int wm = warp & 3;          // 4 warps in m -> 32 rows each
    const int wn = warp >> 2;         // 2 warps in n -> 64 cols each
    const int m0 = blockIdx.y * BM;
    const int n0 = blockIdx.x * BN;

    // ---- cp.async: thread t owns one 128B row of [A(128) | B(128)] ----
    const char* srcRow = (tid < 128)
        ? (const char*)(g_xh    + (size_t)(m0 + tid) * KDIM)
        : (const char*)(g_weffh + (size_t)(n0 + tid - 128) * KDIM);
    const uint32_t dstRow = sbase + (uint32_t)tid * 128;
    const int rsw = tid & 7;                               // store swizzle

    // ---- ldmatrix per-lane addressing ----
    const int lr = lane & 7;
    const int g1 = (lane >> 3) & 1;
    const int g2 = lane >> 4;
    const uint32_t aOff = (uint32_t)(wm * 32 + lr + (g1 << 3)) * 128;
    const uint32_t bOff = (uint32_t)(wn * 64 + lr + (g2 << 3)) * 128;

    float acc[2][8][4];
    #pragma unroll
    for (int i = 0; i < 2; i++)
        #pragma unroll
        for (int j = 0; j < 8; j++)
            #pragma unroll
            for (int c = 0; c < 4; c++) acc[i][j][c] = 0.f;

    // ---- stage loader: 8 chunks x 16B for this thread's row ----
    auto load_stage = [&](int st, int kt) {
        uint32_t sa = dstRow + (uint32_t)st * STAGE_BYTES;
        const char* g = srcRow + (size_t)kt * (BK * 2);
        #pragma unroll
        for (int c = 0; c < 8; c++)
            cp16(sa + (uint32_t)((c ^ rsw) << 4), g + c * 16);
    };

    // ---- prologue: prefetch 2 stages ----
    load_stage(0, 0); cp_commit();
    load_stage(1, 1); cp_commit();

    int st = 0;
    for (int kt = 0; kt < KTILES; kt++) {
        cp_wait<1>();
        __syncthreads();

        if (kt + 2 < KTILES) {
            int st2 = st + 2; if (st2 >= STAGES) st2 -= STAGES;
            load_stage(st2, kt + 2);
        }
        cp_commit();

        const uint32_t aSt = sbase + (uint32_t)st * STAGE_BYTES + aOff;
        const uint32_t bSt = sbase + (uint32_t)st * STAGE_BYTES + A_BYTES + bOff;

        #pragma unroll
        for (int s = 0; s < 4; s++) {           // 4 k-steps of k16
            uint32_t a[2][4], b[4][4];
            const uint32_t xA = (uint32_t)(((2 * s + g2) ^ lr) << 4);
            const uint32_t xB = (uint32_t)(((2 * s + g1) ^ lr) << 4);
            #pragma unroll
            for (int mt = 0; mt < 2; mt++) ldsm4(a[mt], aSt + mt * 2048 + xA);
            #pragma unroll
            for (int p = 0; p < 4; p++)    ldsm4(b[p], bSt + p * 2048 + xB);
            #pragma unroll
            for (int mt = 0; mt < 2; mt++) {
                #pragma unroll
                for (int p = 0; p < 4; p++) {
                    mma16(acc[mt][2 * p],     a[mt], b[p][0], b[p][1]);
                    mma16(acc[mt][2 * p + 1], a[mt], b[p][2], b[p][3]);
                }
            }
        }
        if (++st == STAGES) st = 0;
    }

    // ---- epilogue: add bias, store float2 ----
    const int mrow = m0 + wm * 32 + (lane >> 2);
    const int ncol = n0 + wn * 64 + 2 * (lane & 3);
    float2 bv[8];
    #pragma unroll
    for (int nt = 0; nt < 8; nt++)
        bv[nt] = *reinterpret_cast<const float2*>(bias + ncol + nt * 8);

    #pragma unroll
    for (int mt = 0; mt < 2; mt++) {
        float* r0 = out + (size_t)(mrow + mt * 16) * NDIM + ncol;
        float* r1 = out + (size_t)(mrow + mt * 16 + 8) * NDIM + ncol;
        #pragma unroll
        for (int nt = 0; nt < 8; nt++) {
            float2 v0 = make_float2(acc[mt][nt][0] + bv[nt].x, acc[mt][nt][1] + bv[nt].y);
            float2 v1 = make_float2(acc[mt][nt][2] + bv[nt].x, acc[mt][nt][3] + bv[nt].y);
            *reinterpret_cast<float2*>(r0 + nt * 8) = v0;
            *reinterpret_cast<float2*>(r1 + nt * 8) = v1;
        }
    }
}

// ---------------- launch ----------------------------------------------------
extern "C" void kernel_launch(void* const* d_in, const int* in_sizes, int n_in,
                              void* d_out, int out_size) {
    const float* x    = (const float*)d_in[0];
    const int*   qw   = (const int*)d_in[1];
    const float* ws   = (const float*)d_in[2];
    const float* pd   = (const float*)d_in[3];
    const float* pu   = (const float*)d_in[4];
    const float* wt   = (const float*)d_in[5];
    const float* bias = (const float*)d_in[6];
    float* out = (float*)d_out;

    // fused: x->fp16 rounding + W_eff build (independent, one launch)
    prologue_kernel<<<RX_BLOCKS + PW_BLOCKS, 256>>>(
        (const float4*)x, qw, ws, pd, pu, wt);

    // main GEMM
    cudaFuncSetAttribute(gemm_fp16_kernel, cudaFuncAttributeMaxDynamicSharedMemorySize, SMEM_TOTAL);
    gemm_fp16_kernel<<<dim3(NDIM / BN, MDIM / BM), 256, SMEM_TOTAL>>>(bias, out);
}

// round 7
// speedup vs baseline: 1.1277x; 1.0968x over previous
#include <cuda_runtime.h>
#include <cuda_fp16.h>
#include <cstdint>

// Problem dims (fixed by the dataset)
#define MDIM 8192
#define KDIM 4096
#define NDIM 4096

// ---------------- device scratch (sanctioned: __device__ globals) ----------
__device__ __half g_weffh[(size_t)NDIM * KDIM];  // 32 MB: dequant + lora folded, fp16
__device__ __half g_xh[(size_t)MDIM * KDIM];     // 64 MB: x rounded to fp16 (RN)

// ---------------- helpers ---------------------------------------------------
__device__ __forceinline__ uint32_t smem_u32(const void* p) {
    uint32_t a;
    asm("{ .reg .u64 t; cvta.to.shared.u64 t, %1; cvt.u32.u64 %0, t; }" : "=r"(a) : "l"(p));
    return a;
}
__device__ __forceinline__ void cp16(uint32_t dst, const void* src) {
    asm volatile("cp.async.cg.shared.global [%0], [%1], 16;" :: "r"(dst), "l"(src));
}
__device__ __forceinline__ void cp_commit() {
    asm volatile("cp.async.commit_group;" ::: "memory");
}
template <int N>
__device__ __forceinline__ void cp_wait() {
    asm volatile("cp.async.wait_group %0;" :: "n"(N) : "memory");
}
__device__ __forceinline__ void ldsm4(uint32_t r[4], uint32_t addr) {
    asm volatile("ldmatrix.sync.aligned.m8n8.x4.shared.b16 {%0,%1,%2,%3}, [%4];"
                 : "=r"(r[0]), "=r"(r[1]), "=r"(r[2]), "=r"(r[3]) : "r"(addr));
}
__device__ __forceinline__ void mma16(float c[4], const uint32_t a[4],
                                      uint32_t b0, uint32_t b1) {
    asm volatile("mma.sync.aligned.m16n8k16.row.col.f32.f16.f16.f32 "
                 "{%0,%1,%2,%3}, {%4,%5,%6,%7}, {%8,%9}, {%0,%1,%2,%3};"
                 : "+f"(c[0]), "+f"(c[1]), "+f"(c[2]), "+f"(c[3])
                 : "r"(a[0]), "r"(a[1]), "r"(a[2]), "r"(a[3]), "r"(b0), "r"(b1));
}

// ---------------- fused prologue: round x AND build W_eff ------------------
// blocks [0, RX_BLOCKS): round x to fp16
// blocks [RX_BLOCKS, RX_BLOCKS + PW_BLOCKS): dequant + lora -> g_weffh
#define RX_BLOCKS ((MDIM * KDIM) / 1024)          // 32768, 256 thr x float4
#define PW_BX (KDIM / 512)                        // 8
#define PW_BY (NDIM / 16)                         // 256
#define PW_BLOCKS (PW_BX * PW_BY)                 // 2048

__global__ void __launch_bounds__(256) prologue_kernel(
    const float4* __restrict__ x,
    const int* __restrict__ qweight, const float* __restrict__ wscales,
    const float* __restrict__ proj_down, const float* __restrict__ proj_up,
    const float* __restrict__ wtscale)
{
    const int tid = threadIdx.x;
    if (blockIdx.x < RX_BLOCKS) {
        // ---- round x to fp16 ----
        int i = blockIdx.x * 256 + tid;
        float4 v = x[i];
        __half2* gx = reinterpret_cast<__half2*>(g_xh);
        gx[2 * i + 0] = __floats2half2_rn(v.x, v.y);
        gx[2 * i + 1] = __floats2half2_rn(v.z, v.w);
        return;
    }
    // ---- W_eff = dequant(q,scale) + wtscale * up@down ----
    const int pbid = blockIdx.x - RX_BLOCKS;
    const int bx = pbid & (PW_BX - 1);
    const int by = pbid / PW_BX;

    __shared__ float up_s[16 * 32];
    const int n0 = by * 16;
    #pragma unroll
    for (int j = tid; j < 512; j += 256) {
        int n = j >> 5, r = j & 31;
        up_s[j] = proj_up[(size_t)(n0 + n) * 32 + r];
    }
    __syncthreads();
    const float wt = wtscale[0];
    const int k2 = bx * 256 + tid;   // pair index; k = 2*k2, 2*k2+1

    float ae[16], ao[16];
    #pragma unroll
    for (int n = 0; n < 16; n++) { ae[n] = 0.f; ao[n] = 0.f; }
    #pragma unroll 4
    for (int r = 0; r < 32; r++) {
        float2 d2 = *reinterpret_cast<const float2*>(proj_down + (size_t)r * KDIM + 2 * k2);
        #pragma unroll
        for (int n = 0; n < 16; n++) {
            float u = up_s[n * 32 + r];
            ae[n] = fmaf(u, d2.x, ae[n]);
            ao[n] = fmaf(u, d2.y, ao[n]);
        }
    }
    const int g = k2 >> 5;  // (2*k2)/64
    #pragma unroll
    for (int n = 0; n < 16; n++) {
        int q = qweight[(size_t)(n0 + n) * (KDIM / 2) + k2];
        float s = wscales[(size_t)g * NDIM + (n0 + n)];
        float we = fmaf((float)((q & 15) - 8), s, wt * ae[n]);
        float wo = fmaf((float)(((q >> 4) & 15) - 8), s, wt * ao[n]);
        *reinterpret_cast<__half2*>(g_weffh + (size_t)(n0 + n) * KDIM + 2 * k2) =
            __floats2half2_rn(we, wo);
    }
}

// ---------------- GEMM (exact R4 config: best known, 1218us) ---------------
// out[m0:m0+128, n0:n0+128] = g_xh @ g_weffh^T + bias   (fp32 accumulate)
// 128 threads, 64x64 warp tiles, coarse register-fragment double buffering.
#define BM 128
#define BN 128
#define BK 64
#define STAGES 3
#define KTILES (KDIM / BK)            // 64
#define A_BYTES (BM * BK * 2)         // 16384
#define STAGE_BYTES (2 * A_BYTES)     // 32768 (A then B)
#define SMEM_TOTAL (STAGES * STAGE_BYTES)

__global__ void __launch_bounds__(128, 2) gemm_fp16_kernel(
    const float* __restrict__ bias, float* __restrict__ out)
{
    extern __shared__ char smem_raw[];
    const uint32_t sbase = smem_u32(smem_raw);

    const int tid  = threadIdx.x;
    const int lane = tid & 31;
    const int warp = tid >> 5;
    const int wm = warp & 1;          // 2 warps in m -> warp tile 64 rows
    const int wn = warp >> 1;         // 2 warps in n -> warp tile 64 cols
    const int m0 = blockIdx.y * BM;
    const int n0 = blockIdx.x * BN;

    // ---- cp.async source/dest (thread t owns A row t and B row t) ----
    const char* srcA = (const char*)(g_xh    + (size_t)(m0 + tid) * KDIM);
    const char* srcB = (const char*)(g_weffh + (size_t)(n0 + tid) * KDIM);
    const uint32_t dstRow = sbase + (uint32_t)tid * 128;  // within-stage row base (128B rows)
    const int rsw = tid & 7;                               // store swizzle

    // ---- ldmatrix per-lane addressing ----
    const int lr = lane & 7;
    const int g1 = (lane >> 3) & 1;
    const int g2 = lane >> 4;
    const uint32_t aOff = (uint32_t)(wm * 64 + lr + (g1 << 3)) * 128;
    const uint32_t bOff = (uint32_t)(wn * 64 + lr + (g2 << 3)) * 128;

    float acc[4][8][4];
    #pragma unroll
    for (int i = 0; i < 4; i++)
        #pragma unroll
        for (int j = 0; j < 8; j++)
            #pragma unroll
            for (int c = 0; c < 4; c++) acc[i][j][c] = 0.f;

    // ---- stage loader: 8 chunks x 16B per row = 64 halves (BK) ----
    auto load_stage = [&](int st, int kt) {
        uint32_t sa = dstRow + (uint32_t)st * STAGE_BYTES;
        const char* ga = srcA + (size_t)kt * (BK * 2);
        const char* gb = srcB + (size_t)kt * (BK * 2);
        #pragma unroll
        for (int c = 0; c < 8; c++) {
            uint32_t off = (uint32_t)((c ^ rsw) << 4);
            cp16(sa + off,           ga + c * 16);
            cp16(sa + A_BYTES + off, gb + c * 16);
        }
    };

    // fragment double buffers
    uint32_t fa[2][4][4], fb[2][4][4];

    // load all fragments of k-step s from stage st into buffer buf
    auto ldsm_step = [&](int buf, int st, int s) {
        const uint32_t aSt = sbase + (uint32_t)st * STAGE_BYTES + aOff;
        const uint32_t bSt = sbase + (uint32_t)st * STAGE_BYTES + A_BYTES + bOff;
        const uint32_t xA = (uint32_t)(((2 * s + g2) ^ lr) << 4);
        const uint32_t xB = (uint32_t)(((2 * s + g1) ^ lr) << 4);
        #pragma unroll
        for (int mt = 0; mt < 4; mt++) {
            ldsm4(fa[buf][mt], aSt + mt * 2048 + xA);
            ldsm4(fb[buf][mt], bSt + mt * 2048 + xB);
        }
    };

    auto mma_step = [&](int buf) {
        #pragma unroll
        for (int mt = 0; mt < 4; mt++) {
            #pragma unroll
            for (int p = 0; p < 4; p++) {
                mma16(acc[mt][2 * p],     fa[buf][mt], fb[buf][p][0], fb[buf][p][1]);
                mma16(acc[mt][2 * p + 1], fa[buf][mt], fb[buf][p][2], fb[buf][p][3]);
            }
        }
    };

    // ---- prologue: prefetch 2 stages, then preload step-0 fragments ----
    load_stage(0, 0); cp_commit();
    load_stage(1, 1); cp_commit();
    cp_wait<1>();
    __syncthreads();
    ldsm_step(0, 0, 0);

    int st = 0;
    for (int kt = 0; kt < KTILES; kt++) {
        // prefetch kt+2 into the stage consumed at kt-1
        if (kt + 2 < KTILES) {
            int st2 = st + 2; if (st2 >= STAGES) st2 -= STAGES;
            load_stage(st2, kt + 2);
        }
        cp_commit();

        int stn = st + 1; if (stn >= STAGES) stn = 0;

        #pragma unroll
        for (int s = 0; s < 4; s++) {
            const int cur = s & 1;
            if (s < 3) {
                ldsm_step(cur ^ 1, st, s + 1);   // prefetch next step's fragments
                mma_step(cur);
            } else {
                mma_step(cur);                    // issue last MMAs before the sync
                if (kt + 1 < KTILES) {
                    cp_wait<1>();
                    __syncthreads();
                    ldsm_step(cur ^ 1, stn, 0);   // preload next tile's step 0
                }
            }
        }
        st = stn;
    }

    // ---- epilogue: add bias, store float2 ----
    const int mrow = m0 + wm * 64 + (lane >> 2);
    const int ncol = n0 + wn * 64 + 2 * (lane & 3);
    float2 bv[8];
    #pragma unroll
    for (int nt = 0; nt < 8; nt++)
        bv[nt] = *reinterpret_cast<const float2*>(bias + ncol + nt * 8);

    #pragma unroll
    for (int mt = 0; mt < 4; mt++) {
        float* r0 = out + (size_t)(mrow + mt * 16) * NDIM + ncol;
        float* r1 = out + (size_t)(mrow + mt * 16 + 8) * NDIM + ncol;
        #pragma unroll
        for (int nt = 0; nt < 8; nt++) {
            float2 v0 = make_float2(acc[mt][nt][0] + bv[nt].x, acc[mt][nt][1] + bv[nt].y);
            float2 v1 = make_float2(acc[mt][nt][2] + bv[nt].x, acc[mt][nt][3] + bv[nt].y);
            *reinterpret_cast<float2*>(r0 + nt * 8) = v0;
            *reinterpret_cast<float2*>(r1 + nt * 8) = v1;
        }
    }
}

// ---------------- launch ----------------------------------------------------
extern "C" void kernel_launch(void* const* d_in, const int* in_sizes, int n_in,
                              void* d_out, int out_size) {
    const float* x    = (const float*)d_in[0];
    const int*   qw   = (const int*)d_in[1];
    const float* ws   = (const float*)d_in[2];
    const float* pd   = (const float*)d_in[3];
    const float* pu   = (const float*)d_in[4];
    const float* wt   = (const float*)d_in[5];
    const float* bias = (const float*)d_in[6];
    float* out = (float*)d_out;

    // fused: x->fp16 rounding + W_eff build (independent, one launch)
    prologue_kernel<<<RX_BLOCKS + PW_BLOCKS, 256>>>(
        (const float4*)x, qw, ws, pd, pu, wt);

    // main GEMM (exact R4 configuration)
    cudaFuncSetAttribute(gemm_fp16_kernel, cudaFuncAttributeMaxDynamicSharedMemorySize, SMEM_TOTAL);
    gemm_fp16_kernel<<<dim3(NDIM / BN, MDIM / BM), 128, SMEM_TOTAL>>>(bias, out);
}

// round 8
// speedup vs baseline: 1.2885x; 1.1426x over previous
#include <cuda_runtime.h>
#include <cuda_fp16.h>
#include <cstdint>

// Problem dims (fixed by the dataset)
#define MDIM 8192
#define KDIM 4096
#define NDIM 4096

// ---------------- device scratch (sanctioned: __device__ globals) ----------
__device__ __half g_weffh[(size_t)NDIM * KDIM];  // 32 MB: dequant + lora folded, fp16
__device__ __half g_xh[(size_t)MDIM * KDIM];     // 64 MB: x rounded to fp16 (RN)

// ---------------- helpers ---------------------------------------------------
__device__ __forceinline__ uint32_t smem_u32(const void* p) {
    uint32_t a;
    asm("{ .reg .u64 t; cvta.to.shared.u64 t, %1; cvt.u32.u64 %0, t; }" : "=r"(a) : "l"(p));
    return a;
}
__device__ __forceinline__ void cp16(uint32_t dst, const void* src) {
    asm volatile("cp.async.cg.shared.global [%0], [%1], 16;" :: "r"(dst), "l"(src));
}
__device__ __forceinline__ void cp_commit() {
    asm volatile("cp.async.commit_group;" ::: "memory");
}
template <int N>
__device__ __forceinline__ void cp_wait() {
    asm volatile("cp.async.wait_group %0;" :: "n"(N) : "memory");
}
__device__ __forceinline__ void ldsm4(uint32_t r[4], uint32_t addr) {
    asm volatile("ldmatrix.sync.aligned.m8n8.x4.shared.b16 {%0,%1,%2,%3}, [%4];"
                 : "=r"(r[0]), "=r"(r[1]), "=r"(r[2]), "=r"(r[3]) : "r"(addr));
}
__device__ __forceinline__ void mma16(float c[4], const uint32_t a[4],
                                      uint32_t b0, uint32_t b1) {
    asm volatile("mma.sync.aligned.m16n8k16.row.col.f32.f16.f16.f32 "
                 "{%0,%1,%2,%3}, {%4,%5,%6,%7}, {%8,%9}, {%0,%1,%2,%3};"
                 : "+f"(c[0]), "+f"(c[1]), "+f"(c[2]), "+f"(c[3])
                 : "r"(a[0]), "r"(a[1]), "r"(a[2]), "r"(a[3]), "r"(b0), "r"(b1));
}

// ---------------- kernel 1: round x to fp16 (RN) ----------------------------
__global__ void __launch_bounds__(256) round_x_kernel(const float4* __restrict__ x,
                                                      __half2* __restrict__ gx) {
    int i = blockIdx.x * 256 + threadIdx.x;
    float4 v = x[i];
    gx[2 * i + 0] = __floats2half2_rn(v.x, v.y);
    gx[2 * i + 1] = __floats2half2_rn(v.z, v.w);
}

// ---------------- kernel 2: W_eff = dequant(q,scale) + wtscale * up@down ---
__global__ void __launch_bounds__(256) prep_weight_kernel(
    const int* __restrict__ qweight, const float* __restrict__ wscales,
    const float* __restrict__ proj_down, const float* __restrict__ proj_up,
    const float* __restrict__ wtscale)
{
    __shared__ float up_s[16 * 32];
    const int n0 = blockIdx.y * 16;
    const int tid = threadIdx.x;
    #pragma unroll
    for (int j = tid; j < 512; j += 256) {
        int n = j >> 5, r = j & 31;
        up_s[j] = proj_up[(size_t)(n0 + n) * 32 + r];
    }
    __syncthreads();
    const float wt = wtscale[0];
    const int k2 = blockIdx.x * 256 + tid;   // pair index; k = 2*k2, 2*k2+1

    float ae[16], ao[16];
    #pragma unroll
    for (int n = 0; n < 16; n++) { ae[n] = 0.f; ao[n] = 0.f; }
    #pragma unroll 4
    for (int r = 0; r < 32; r++) {
        float2 d2 = *reinterpret_cast<const float2*>(proj_down + (size_t)r * KDIM + 2 * k2);
        #pragma unroll
        for (int n = 0; n < 16; n++) {
            float u = up_s[n * 32 + r];
            ae[n] = fmaf(u, d2.x, ae[n]);
            ao[n] = fmaf(u, d2.y, ao[n]);
        }
    }
    const int g = k2 >> 5;  // (2*k2)/64
    #pragma unroll
    for (int n = 0; n < 16; n++) {
        int q = qweight[(size_t)(n0 + n) * (KDIM / 2) + k2];
        float s = wscales[(size_t)g * NDIM + (n0 + n)];
        float we = fmaf((float)((q & 15) - 8), s, wt * ae[n]);
        float wo = fmaf((float)(((q >> 4) & 15) - 8), s, wt * ao[n]);
        *reinterpret_cast<__half2*>(g_weffh + (size_t)(n0 + n) * KDIM + 2 * k2) =
            __floats2half2_rn(we, wo);
    }
}

// ---------------- GEMM: 256x128 CTA tile, 256 threads, 1 CTA/SM ------------
// out[m0:m0+256, n0:n0+128] = g_xh @ g_weffh^T + bias   (fp32 accumulate)
// Per-warp schedule is identical to the proven R4 kernel (64x64 warp tile,
// coarse fragment double buffering); the larger M-tile halves B-side cp.async
// instruction traffic, which the R7 profile showed is the binding pipe
// (L1=80.6% vs tensor=39.7%).
#define BM 256
#define BN 128
#define BK 64
#define STAGES 3
#define KTILES (KDIM / BK)            // 64
#define A_BYTES (BM * BK * 2)         // 32768
#define B_BYTES (BN * BK * 2)         // 16384
#define STAGE_BYTES (A_BYTES + B_BYTES)  // 49152
#define SMEM_TOTAL (STAGES * STAGE_BYTES)  // 147456

__global__ void __launch_bounds__(256, 1) gemm_fp16_kernel(
    const float* __restrict__ bias, float* __restrict__ out)
{
    extern __shared__ char smem_raw[];
    const uint32_t sbase = smem_u32(smem_raw);

    const int tid  = threadIdx.x;
    const int lane = tid & 31;
    const int warp = tid >> 5;
    const int wm = warp & 3;          // 4 warps in m -> warp tile 64 rows
    const int wn = warp >> 2;         // 2 warps in n -> warp tile 64 cols
    const int m0 = blockIdx.y * BM;
    const int n0 = blockIdx.x * BN;

    // ---- cp.async: thread t owns A row t (8 chunks) + half of B row t/2 ----
    const char* srcA = (const char*)(g_xh    + (size_t)(m0 + tid) * KDIM);
    const char* srcB = (const char*)(g_weffh + (size_t)(n0 + (tid >> 1)) * KDIM);
    const uint32_t dstA = sbase + (uint32_t)tid * 128;
    const uint32_t dstB = sbase + A_BYTES + (uint32_t)(tid >> 1) * 128;
    const int rswA = tid & 7;
    const int rswB = (tid >> 1) & 7;
    const int bc0  = (tid & 1) * 4;   // B chunk base for this thread

    // ---- ldmatrix per-lane addressing ----
    const int lr = lane & 7;
    const int g1 = (lane >> 3) & 1;
    const int g2 = lane >> 4;
    const uint32_t aOff = (uint32_t)(wm * 64 + lr + (g1 << 3)) * 128;
    const uint32_t bOff = (uint32_t)(wn * 64 + lr + (g2 << 3)) * 128;

    float acc[4][8][4];
    #pragma unroll
    for (int i = 0; i < 4; i++)
        #pragma unroll
        for (int j = 0; j < 8; j++)
            #pragma unroll
            for (int c = 0; c < 4; c++) acc[i][j][c] = 0.f;

    // ---- stage loader: 8 A-chunks + 4 B-chunks per thread ----
    auto load_stage = [&](int st, int kt) {
        const uint32_t so = (uint32_t)st * STAGE_BYTES;
        const char* ga = srcA + (size_t)kt * (BK * 2);
        const char* gb = srcB + (size_t)kt * (BK * 2);
        #pragma unroll
        for (int c = 0; c < 8; c++)
            cp16(dstA + so + (uint32_t)((c ^ rswA) << 4), ga + c * 16);
        #pragma unroll
        for (int i = 0; i < 4; i++) {
            int c = bc0 + i;
            cp16(dstB + so + (uint32_t)((c ^ rswB) << 4), gb + c * 16);
        }
    };

    // fragment double buffers (same shape as R4)
    uint32_t fa[2][4][4], fb[2][4][4];

    auto ldsm_step = [&](int buf, int st, int s) {
        const uint32_t aSt = sbase + (uint32_t)st * STAGE_BYTES + aOff;
        const uint32_t bSt = sbase + (uint32_t)st * STAGE_BYTES + A_BYTES + bOff;
        const uint32_t xA = (uint32_t)(((2 * s + g2) ^ lr) << 4);
        const uint32_t xB = (uint32_t)(((2 * s + g1) ^ lr) << 4);
        #pragma unroll
        for (int mt = 0; mt < 4; mt++) {
            ldsm4(fa[buf][mt], aSt + mt * 2048 + xA);
            ldsm4(fb[buf][mt], bSt + mt * 2048 + xB);
        }
    };

    auto mma_step = [&](int buf) {
        #pragma unroll
        for (int mt = 0; mt < 4; mt++) {
            #pragma unroll
            for (int p = 0; p < 4; p++) {
                mma16(acc[mt][2 * p],     fa[buf][mt], fb[buf][p][0], fb[buf][p][1]);
                mma16(acc[mt][2 * p + 1], fa[buf][mt], fb[buf][p][2], fb[buf][p][3]);
            }
        }
    };

    // ---- prologue: prefetch 2 stages, then preload step-0 fragments ----
    load_stage(0, 0); cp_commit();
    load_stage(1, 1); cp_commit();
    cp_wait<1>();
    __syncthreads();
    ldsm_step(0, 0, 0);

    int st = 0;
    for (int kt = 0; kt < KTILES; kt++) {
        // prefetch kt+2 into the stage consumed at kt-1
        if (kt + 2 < KTILES) {
            int st2 = st + 2; if (st2 >= STAGES) st2 -= STAGES;
            load_stage(st2, kt + 2);
        }
        cp_commit();

        int stn = st + 1; if (stn >= STAGES) stn = 0;

        #pragma unroll
        for (int s = 0; s < 4; s++) {
            const int cur = s & 1;
            if (s < 3) {
                ldsm_step(cur ^ 1, st, s + 1);   // prefetch next step's fragments
                mma_step(cur);
            } else {
                mma_step(cur);                    // last MMAs cover the barrier
                if (kt + 1 < KTILES) {
                    cp_wait<1>();
                    __syncthreads();
                    ldsm_step(cur ^ 1, stn, 0);   // preload next tile's step 0
                }
            }
        }
        st = stn;
    }

    // ---- epilogue: add bias, store float2 ----
    const int mrow = m0 + wm * 64 + (lane >> 2);
    const int ncol = n0 + wn * 64 + 2 * (lane & 3);
    float2 bv[8];
    #pragma unroll
    for (int nt = 0; nt < 8; nt++)
        bv[nt] = *reinterpret_cast<const float2*>(bias + ncol + nt * 8);

    #pragma unroll
    for (int mt = 0; mt < 4; mt++) {
        float* r0 = out + (size_t)(mrow + mt * 16) * NDIM + ncol;
        float* r1 = out + (size_t)(mrow + mt * 16 + 8) * NDIM + ncol;
        #pragma unroll
        for (int nt = 0; nt < 8; nt++) {
            float2 v0 = make_float2(acc[mt][nt][0] + bv[nt].x, acc[mt][nt][1] + bv[nt].y);
            float2 v1 = make_float2(acc[mt][nt][2] + bv[nt].x, acc[mt][nt][3] + bv[nt].y);
            *reinterpret_cast<float2*>(r0 + nt * 8) = v0;
            *reinterpret_cast<float2*>(r1 + nt * 8) = v1;
        }
    }
}

// ---------------- launch ----------------------------------------------------
extern "C" void kernel_launch(void* const* d_in, const int* in_sizes, int n_in,
                              void* d_out, int out_size) {
    const float* x    = (const float*)d_in[0];
    const int*   qw   = (const int*)d_in[1];
    const float* ws   = (const float*)d_in[2];
    const float* pd   = (const float*)d_in[3];
    const float* pu   = (const float*)d_in[4];
    const float* wt   = (const float*)d_in[5];
    const float* bias = (const float*)d_in[6];
    float* out = (float*)d_out;

    // x -> fp16 (RN) into g_xh
    {
        __half2* gx;
        cudaGetSymbolAddress((void**)&gx, g_xh);
        int n4 = (MDIM * KDIM) / 4;
        round_x_kernel<<<n4 / 256, 256>>>((const float4*)x, gx);
    }
    // W_eff = dequant + lora, fp16-rounded
    prep_weight_kernel<<<dim3(KDIM / 512, NDIM / 16), 256>>>(qw, ws, pd, pu, wt);

    // main GEMM
    cudaFuncSetAttribute(gemm_fp16_kernel, cudaFuncAttributeMaxDynamicSharedMemorySize, SMEM_TOTAL);
    gemm_fp16_kernel<<<dim3(NDIM / BN, MDIM / BM), 256, SMEM_TOTAL>>>(bias, out);
}

// round 10
// speedup vs baseline: 2.1582x; 1.6750x over previous
#include <cuda_runtime.h>
#include <cuda_fp16.h>
#include <cstdint>

// Problem dims (fixed by the dataset)
#define MDIM 8192
#define KDIM 4096
#define NDIM 4096
#define KT64 (KDIM / 64)   // 64 k-tiles of 64 halves

// ---------------- device scratch (sanctioned: __device__ globals) ----------
// Stored TILE-MAJOR and PRE-SWIZZLED so the GEMM can fetch one contiguous
// slab per stage with a single cp.async.bulk:
//   g_xh    : [m-block(256)][ktile][row 0..255][128B swizzled row]   (64 MB)
//   g_weffh : [n-block(128)][ktile][row 0..127][128B swizzled row]   (32 MB)
__device__ __half g_weffh[(size_t)NDIM * KDIM];
__device__ __half g_xh[(size_t)MDIM * KDIM];

// ---------------- helpers ---------------------------------------------------
__device__ __forceinline__ uint32_t h2_as_u32(__half2 h) {
    return *reinterpret_cast<uint32_t*>(&h);
}
__device__ __forceinline__ uint32_t smem_u32(const void* p) {
    uint32_t a;
    asm("{ .reg .u64 t; cvta.to.shared.u64 t, %1; cvt.u32.u64 %0, t; }" : "=r"(a) : "l"(p));
    return a;
}
__device__ __forceinline__ void ldsm4(uint32_t r[4], uint32_t addr) {
    asm volatile("ldmatrix.sync.aligned.m8n8.x4.shared.b16 {%0,%1,%2,%3}, [%4];"
                 : "=r"(r[0]), "=r"(r[1]), "=r"(r[2]), "=r"(r[3]) : "r"(addr));
}
__device__ __forceinline__ void mma16(float c[4], const uint32_t a[4],
                                      uint32_t b0, uint32_t b1) {
    asm volatile("mma.sync.aligned.m16n8k16.row.col.f32.f16.f16.f32 "
                 "{%0,%1,%2,%3}, {%4,%5,%6,%7}, {%8,%9}, {%0,%1,%2,%3};"
                 : "+f"(c[0]), "+f"(c[1]), "+f"(c[2]), "+f"(c[3])
                 : "r"(a[0]), "r"(a[1]), "r"(a[2]), "r"(a[3]), "r"(b0), "r"(b1));
}
__device__ __forceinline__ void bulkcp(uint32_t dst, const void* src,
                                       uint32_t bytes, uint32_t bar) {
    asm volatile(
        "cp.async.bulk.shared::cta.global.mbarrier::complete_tx::bytes "
        "[%0], [%1], %2, [%3];"
        :: "r"(dst), "l"(src), "r"(bytes), "r"(bar) : "memory");
}
#define MBARRIER_INIT(addr, count) \
    asm volatile("mbarrier.init.shared.b64 [%0], %1;" \
        :: "r"((uint32_t)(addr)), "r"((uint32_t)(count)) : "memory")
#define MBARRIER_EXPECT_TX(addr, bytes) \
    asm volatile("mbarrier.arrive.expect_tx.shared.b64 _, [%0], %1;" \
        :: "r"((uint32_t)(addr)), "r"((uint32_t)(bytes)) : "memory")
#define MBARRIER_WAIT_PARITY(mbar_smem_addr, phase_parity) do { \
    uint32_t _mbar = (uint32_t)(mbar_smem_addr); \
    uint32_t _parity = (uint32_t)(phase_parity); \
    uint32_t _done; \
    asm volatile("{\n\t.reg .pred p;\n\t" \
        "mbarrier.try_wait.parity.acquire.cta.shared::cta.b64 p, [%1], %2;\n\t" \
        "selp.b32 %0, 1, 0, p;\n\t}" \
        : "=r"(_done) : "r"(_mbar), "r"(_parity) : "memory"); \
    if (!_done) { \
        asm volatile("{\n\t.reg .pred P1;\n\t" \
            "WAIT_LOOP_%=:\n\t" \
            "mbarrier.try_wait.parity.acquire.cta.shared::cta.b64 P1, [%0], %1, 0x989680;\n\t" \
            "@P1 bra.uni WAIT_DONE_%=;\n\t" \
            "bra.uni WAIT_LOOP_%=;\n\t" \
            "WAIT_DONE_%=:\n\t}" \
            :: "r"(_mbar), "r"(_parity) : "memory"); \
    } \
} while (0)

// ---------------- kernel 1: round x to fp16, tiled+swizzled layout ---------
__global__ void __launch_bounds__(256) round_x_kernel(const float4* __restrict__ x) {
    int i = blockIdx.x * 256 + threadIdx.x;       // float4 index over [M,K]
    float4 v = x[i];
    int m = i >> 10;                               // K/4 = 1024 float4 per row
    int k = (i & 1023) * 4;
    int mb = m >> 8, row = m & 255;
    int ktile = k >> 6;
    int c = (k >> 3) & 7;
    size_t off = (((size_t)(mb * KT64 + ktile)) * 256 + row) * 128
               + (uint32_t)((c ^ (row & 7)) << 4) + (k & 7) * 2;
    uint2 w;
    w.x = h2_as_u32(__floats2half2_rn(v.x, v.y));
    w.y = h2_as_u32(__floats2half2_rn(v.z, v.w));
    *reinterpret_cast<uint2*>(reinterpret_cast<char*>(g_xh) + off) = w;
}

// ---------------- kernel 2: W_eff = dequant + lora, tiled+swizzled ----------
__global__ void __launch_bounds__(256) prep_weight_kernel(
    const int* __restrict__ qweight, const float* __restrict__ wscales,
    const float* __restrict__ proj_down, const float* __restrict__ proj_up,
    const float* __restrict__ wtscale)
{
    __shared__ float up_s[16 * 32];
    const int n0 = blockIdx.y * 16;
    const int tid = threadIdx.x;
    #pragma unroll
    for (int j = tid; j < 512; j += 256) {
        int n = j >> 5, r = j & 31;
        up_s[j] = proj_up[(size_t)(n0 + n) * 32 + r];
    }
    __syncthreads();
    const float wt = wtscale[0];
    const int k2 = blockIdx.x * 256 + tid;   // pair index; k = 2*k2, 2*k2+1

    float ae[16], ao[16];
    #pragma unroll
    for (int n = 0; n < 16; n++) { ae[n] = 0.f; ao[n] = 0.f; }
    #pragma unroll 4
    for (int r = 0; r < 32; r++) {
        float2 d2 = *reinterpret_cast<const float2*>(proj_down + (size_t)r * KDIM + 2 * k2);
        #pragma unroll
        for (int n = 0; n < 16; n++) {
            float u = up_s[n * 32 + r];
            ae[n] = fmaf(u, d2.x, ae[n]);
            ao[n] = fmaf(u, d2.y, ao[n]);
        }
    }
    const int g = k2 >> 5;
    const int k = 2 * k2;
    const int ktile = k >> 6;
    const int c = (k >> 3) & 7;
    #pragma unroll
    for (int nn = 0; nn < 16; nn++) {
        int n = n0 + nn;
        int q = qweight[(size_t)n * (KDIM / 2) + k2];
        float s = wscales[(size_t)g * NDIM + n];
        float we = fmaf((float)((q & 15) - 8), s, wt * ae[nn]);
        float wo = fmaf((float)(((q >> 4) & 15) - 8), s, wt * ao[nn]);
        int nb = n >> 7, rowb = n & 127;
        size_t off = (((size_t)(nb * KT64 + ktile)) * 128 + rowb) * 128
                   + (uint32_t)((c ^ (rowb & 7)) << 4) + (k & 7) * 2;
        __half2 hv = __floats2half2_rn(we, wo);
        *reinterpret_cast<__half2*>(reinterpret_cast<char*>(g_weffh) + off) = hv;
    }
}

// ---------------- GEMM: 256x128 tile, bulk-copy fed, mbarrier pipeline -----
#define BM 256
#define BN 128
#define BK 64
#define STAGES 4
#define KTILES KT64                       // 64
#define A_BYTES (BM * BK * 2)             // 32768 (one contiguous slab now)
#define B_BYTES (BN * BK * 2)             // 16384
#define STAGE_BYTES (A_BYTES + B_BYTES)   // 49152
#define OFF_BAR   0
#define OFF_STAGE 1024
#define SMEM_TOTAL (OFF_STAGE + STAGES * STAGE_BYTES)   // 197632

__global__ void __launch_bounds__(256, 1) gemm_fp16_kernel(
    const float* __restrict__ bias, float* __restrict__ out)
{
    extern __shared__ char smem_raw[];
    const uint32_t sbase = smem_u32(smem_raw);
    const uint32_t barB  = sbase + OFF_BAR;
    const uint32_t stg0  = sbase + OFF_STAGE;

    const int tid  = threadIdx.x;
    const int lane = tid & 31;
    const int warp = tid >> 5;
    const int wm = warp & 3;          // 4 warps in m -> warp tile 64 rows
    const int wn = warp >> 2;         // 2 warps in n -> warp tile 64 cols
    const int m0 = blockIdx.y * BM;
    const int n0 = blockIdx.x * BN;

    // contiguous slab bases for this CTA
    const char* gA = reinterpret_cast<const char*>(g_xh)
                   + (size_t)blockIdx.y * KT64 * A_BYTES;
    const char* gB = reinterpret_cast<const char*>(g_weffh)
                   + (size_t)blockIdx.x * KT64 * B_BYTES;

    if (tid == 0) {
        #pragma unroll
        for (int s = 0; s < STAGES; s++) MBARRIER_INIT(barB + s * 8, 1);
    }
    __syncthreads();

    auto issue = [&](int kt) {
        uint32_t b  = barB + (uint32_t)((kt & 3) * 8);
        uint32_t so = stg0 + (uint32_t)(kt & 3) * STAGE_BYTES;
        MBARRIER_EXPECT_TX(b, STAGE_BYTES);
        bulkcp(so,           gA + (size_t)kt * A_BYTES, A_BYTES, b);
        bulkcp(so + A_BYTES, gB + (size_t)kt * B_BYTES, B_BYTES, b);
    };
    if (tid == 0) { issue(0); issue(1); }

    // ---- ldmatrix per-lane addressing (identical to R8) ----
    const int lr = lane & 7;
    const int g1 = (lane >> 3) & 1;
    const int g2 = lane >> 4;
    const uint32_t aOff = (uint32_t)(wm * 64 + lr + (g1 << 3)) * 128;
    const uint32_t bOff = (uint32_t)(wn * 64 + lr + (g2 << 3)) * 128;

    float acc[4][8][4];
    #pragma unroll
    for (int i = 0; i < 4; i++)
        #pragma unroll
        for (int j = 0; j < 8; j++)
            #pragma unroll
            for (int c = 0; c < 4; c++) acc[i][j][c] = 0.f;

    uint32_t fa[2][4][4], fb[2][4][4];
    auto ldsm_step = [&](int buf, int st, int s) {
        const uint32_t aSt = stg0 + (uint32_t)st * STAGE_BYTES + aOff;
        const uint32_t bSt = stg0 + (uint32_t)st * STAGE_BYTES + A_BYTES + bOff;
        const uint32_t xA = (uint32_t)(((2 * s + g2) ^ lr) << 4);
        const uint32_t xB = (uint32_t)(((2 * s + g1) ^ lr) << 4);
        #pragma unroll
        for (int mt = 0; mt < 4; mt++) {
            ldsm4(fa[buf][mt], aSt + mt * 2048 + xA);
            ldsm4(fb[buf][mt], bSt + mt * 2048 + xB);
        }
    };
    auto mma_step = [&](int buf) {
        #pragma unroll
        for (int mt = 0; mt < 4; mt++) {
            #pragma unroll
            for (int p = 0; p < 4; p++) {
                mma16(acc[mt][2 * p],     fa[buf][mt], fb[buf][p][0], fb[buf][p][1]);
                mma16(acc[mt][2 * p + 1], fa[buf][mt], fb[buf][p][2], fb[buf][p][3]);
            }
        }
    };

    for (int kt = 0; kt < KTILES; kt++) {
        const int st = kt & 3;
        // prefetch kt+2 into stage (kt+2)&3 — its last readers (kt-2) were
        // sealed by the barrier inside iteration kt-1.
        if (tid == 0 && kt + 2 < KTILES) issue(kt + 2);

        MBARRIER_WAIT_PARITY(barB + st * 8, (kt >> 2) & 1);
        __syncthreads();

        ldsm_step(0, st, 0);
        #pragma unroll
        for (int s = 0; s < 4; s++) {
            const int cur = s & 1;
            if (s < 3) {
                ldsm_step(cur ^ 1, st, s + 1);
                mma_step(cur);
            } else {
                mma_step(cur);   // issued before next iteration's wait/barrier
            }
        }
    }

    // ---- epilogue: add bias, store float2 ----
    const int mrow = m0 + wm * 64 + (lane >> 2);
    const int ncol = n0 + wn * 64 + 2 * (lane & 3);
    float2 bv[8];
    #pragma unroll
    for (int nt = 0; nt < 8; nt++)
        bv[nt] = *reinterpret_cast<const float2*>(bias + ncol + nt * 8);

    #pragma unroll
    for (int mt = 0; mt < 4; mt++) {
        float* r0 = out + (size_t)(mrow + mt * 16) * NDIM + ncol;
        float* r1 = out + (size_t)(mrow + mt * 16 + 8) * NDIM + ncol;
        #pragma unroll
        for (int nt = 0; nt < 8; nt++) {
            float2 v0 = make_float2(acc[mt][nt][0] + bv[nt].x, acc[mt][nt][1] + bv[nt].y);
            float2 v1 = make_float2(acc[mt][nt][2] + bv[nt].x, acc[mt][nt][3] + bv[nt].y);
            *reinterpret_cast<float2*>(r0 + nt * 8) = v0;
            *reinterpret_cast<float2*>(r1 + nt * 8) = v1;
        }
    }
}

// ---------------- launch ----------------------------------------------------
extern "C" void kernel_launch(void* const* d_in, const int* in_sizes, int n_in,
                              void* d_out, int out_size) {
    const float* x    = (const float*)d_in[0];
    const int*   qw   = (const int*)d_in[1];
    const float* ws   = (const float*)d_in[2];
    const float* pd   = (const float*)d_in[3];
    const float* pu   = (const float*)d_in[4];
    const float* wt   = (const float*)d_in[5];
    const float* bias = (const float*)d_in[6];
    float* out = (float*)d_out;

    // x -> fp16 (RN) into tiled/swizzled g_xh
    round_x_kernel<<<(MDIM * KDIM / 4) / 256, 256>>>((const float4*)x);
    // W_eff = dequant + lora, fp16, tiled/swizzled
    prep_weight_kernel<<<dim3(KDIM / 512, NDIM / 16), 256>>>(qw, ws, pd, pu, wt);

    // main GEMM
    cudaFuncSetAttribute(gemm_fp16_kernel, cudaFuncAttributeMaxDynamicSharedMemorySize, SMEM_TOTAL);
    gemm_fp16_kernel<<<dim3(NDIM / BN, MDIM / BM), 256, SMEM_TOTAL>>>(bias, out);
}

// round 11
// speedup vs baseline: 2.2801x; 1.0565x over previous
#include <cuda_runtime.h>
#include <cuda_fp16.h>
#include <cstdint>

// Problem dims (fixed by the dataset)
#define MDIM 8192
#define KDIM 4096
#define NDIM 4096
#define KT64 (KDIM / 64)   // 64 k-tiles of 64 halves

// ---------------- device scratch (sanctioned: __device__ globals) ----------
// TILE-MAJOR, PRE-SWIZZLED:
//   g_xh    : [m-block(128)][ktile][row 0..127][128B swizzled row]   (64 MB)
//   g_weffh : [n-block(128)][ktile][row 0..127][128B swizzled row]   (32 MB)
__device__ __half g_weffh[(size_t)NDIM * KDIM];
__device__ __half g_xh[(size_t)MDIM * KDIM];

// ---------------- helpers ---------------------------------------------------
__device__ __forceinline__ uint32_t h2_as_u32(__half2 h) {
    return *reinterpret_cast<uint32_t*>(&h);
}
__device__ __forceinline__ uint32_t smem_u32(const void* p) {
    uint32_t a;
    asm("{ .reg .u64 t; cvta.to.shared.u64 t, %1; cvt.u32.u64 %0, t; }" : "=r"(a) : "l"(p));
    return a;
}
__device__ __forceinline__ void ldsm4(uint32_t r[4], uint32_t addr) {
    asm volatile("ldmatrix.sync.aligned.m8n8.x4.shared.b16 {%0,%1,%2,%3}, [%4];"
                 : "=r"(r[0]), "=r"(r[1]), "=r"(r[2]), "=r"(r[3]) : "r"(addr));
}
__device__ __forceinline__ void mma16(float c[4], const uint32_t a[4],
                                      uint32_t b0, uint32_t b1) {
    asm volatile("mma.sync.aligned.m16n8k16.row.col.f32.f16.f16.f32 "
                 "{%0,%1,%2,%3}, {%4,%5,%6,%7}, {%8,%9}, {%0,%1,%2,%3};"
                 : "+f"(c[0]), "+f"(c[1]), "+f"(c[2]), "+f"(c[3])
                 : "r"(a[0]), "r"(a[1]), "r"(a[2]), "r"(a[3]), "r"(b0), "r"(b1));
}
__device__ __forceinline__ void bulkcp(uint32_t dst, const void* src,
                                       uint32_t bytes, uint32_t bar) {
    asm volatile(
        "cp.async.bulk.shared::cta.global.mbarrier::complete_tx::bytes "
        "[%0], [%1], %2, [%3];"
        :: "r"(dst), "l"(src), "r"(bytes), "r"(bar) : "memory");
}
#define MBARRIER_INIT(addr, count) \
    asm volatile("mbarrier.init.shared.b64 [%0], %1;" \
        :: "r"((uint32_t)(addr)), "r"((uint32_t)(count)) : "memory")
#define MBARRIER_EXPECT_TX(addr, bytes) \
    asm volatile("mbarrier.arrive.expect_tx.shared.b64 _, [%0], %1;" \
        :: "r"((uint32_t)(addr)), "r"((uint32_t)(bytes)) : "memory")
#define MBARRIER_WAIT_PARITY(mbar_smem_addr, phase_parity) do { \
    uint32_t _mbar = (uint32_t)(mbar_smem_addr); \
    uint32_t _parity = (uint32_t)(phase_parity); \
    uint32_t _done; \
    asm volatile("{\n\t.reg .pred p;\n\t" \
        "mbarrier.try_wait.parity.acquire.cta.shared::cta.b64 p, [%1], %2;\n\t" \
        "selp.b32 %0, 1, 0, p;\n\t}" \
        : "=r"(_done) : "r"(_mbar), "r"(_parity) : "memory"); \
    if (!_done) { \
        asm volatile("{\n\t.reg .pred P1;\n\t" \
            "WAIT_LOOP_%=:\n\t" \
            "mbarrier.try_wait.parity.acquire.cta.shared::cta.b64 P1, [%0], %1, 0x989680;\n\t" \
            "@P1 bra.uni WAIT_DONE_%=;\n\t" \
            "bra.uni WAIT_LOOP_%=;\n\t" \
            "WAIT_DONE_%=:\n\t}" \
            :: "r"(_mbar), "r"(_parity) : "memory"); \
    } \
} while (0)

// ---------------- kernel 1: round x to fp16, tiled+swizzled (128-row blocks)
__global__ void __launch_bounds__(256) round_x_kernel(const float4* __restrict__ x) {
    int i = blockIdx.x * 256 + threadIdx.x;       // float4 index over [M,K]
    float4 v = x[i];
    int m = i >> 10;                               // K/4 = 1024 float4 per row
    int k = (i & 1023) * 4;
    int mb = m >> 7, row = m & 127;
    int ktile = k >> 6;
    int c = (k >> 3) & 7;
    size_t off = (((size_t)(mb * KT64 + ktile)) * 128 + row) * 128
               + (uint32_t)((c ^ (row & 7)) << 4) + (k & 7) * 2;
    uint2 w;
    w.x = h2_as_u32(__floats2half2_rn(v.x, v.y));
    w.y = h2_as_u32(__floats2half2_rn(v.z, v.w));
    *reinterpret_cast<uint2*>(reinterpret_cast<char*>(g_xh) + off) = w;
}

// ---------------- kernel 2: W_eff = dequant + lora, tiled+swizzled ----------
__global__ void __launch_bounds__(256) prep_weight_kernel(
    const int* __restrict__ qweight, const float* __restrict__ wscales,
    const float* __restrict__ proj_down, const float* __restrict__ proj_up,
    const float* __restrict__ wtscale)
{
    __shared__ float up_s[16 * 32];
    const int n0 = blockIdx.y * 16;
    const int tid = threadIdx.x;
    #pragma unroll
    for (int j = tid; j < 512; j += 256) {
        int n = j >> 5, r = j & 31;
        up_s[j] = proj_up[(size_t)(n0 + n) * 32 + r];
    }
    __syncthreads();
    const float wt = wtscale[0];
    const int k2 = blockIdx.x * 256 + tid;   // pair index; k = 2*k2, 2*k2+1

    float ae[16], ao[16];
    #pragma unroll
    for (int n = 0; n < 16; n++) { ae[n] = 0.f; ao[n] = 0.f; }
    #pragma unroll 4
    for (int r = 0; r < 32; r++) {
        float2 d2 = *reinterpret_cast<const float2*>(proj_down + (size_t)r * KDIM + 2 * k2);
        #pragma unroll
        for (int n = 0; n < 16; n++) {
            float u = up_s[n * 32 + r];
            ae[n] = fmaf(u, d2.x, ae[n]);
            ao[n] = fmaf(u, d2.y, ao[n]);
        }
    }
    const int g = k2 >> 5;
    const int k = 2 * k2;
    const int ktile = k >> 6;
    const int c = (k >> 3) & 7;
    #pragma unroll
    for (int nn = 0; nn < 16; nn++) {
        int n = n0 + nn;
        int q = qweight[(size_t)n * (KDIM / 2) + k2];
        float s = wscales[(size_t)g * NDIM + n];
        float we = fmaf((float)((q & 15) - 8), s, wt * ae[nn]);
        float wo = fmaf((float)(((q >> 4) & 15) - 8), s, wt * ao[nn]);
        int nb = n >> 7, rowb = n & 127;
        size_t off = (((size_t)(nb * KT64 + ktile)) * 128 + rowb) * 128
                   + (uint32_t)((c ^ (rowb & 7)) << 4) + (k & 7) * 2;
        __half2 hv = __floats2half2_rn(we, wo);
        *reinterpret_cast<__half2*>(reinterpret_cast<char*>(g_weffh) + off) = hv;
    }
}

// ---------------- GEMM: 128x128 tile, 2 CTAs/SM, bulk-fed ------------------
#define BM 128
#define BN 128
#define BK 64
#define STAGES 3
#define KTILES KT64                       // 64
#define A_BYTES (BM * BK * 2)             // 16384
#define B_BYTES (BN * BK * 2)             // 16384
#define STAGE_BYTES (A_BYTES + B_BYTES)   // 32768
#define OFF_BAR   0
#define OFF_STAGE 1024
#define SMEM_TOTAL (OFF_STAGE + STAGES * STAGE_BYTES)   // 99328 -> 2 CTAs/SM

__global__ void __launch_bounds__(256, 2) gemm_fp16_kernel(
    const float* __restrict__ bias, float* __restrict__ out)
{
    extern __shared__ char smem_raw[];
    const uint32_t sbase = smem_u32(smem_raw);
    const uint32_t barB  = sbase + OFF_BAR;
    const uint32_t stg0  = sbase + OFF_STAGE;

    const int tid  = threadIdx.x;
    const int lane = tid & 31;
    const int warp = tid >> 5;
    const int wm = warp & 3;          // 4 warps in m -> warp tile 32 rows
    const int wn = warp >> 2;         // 2 warps in n -> warp tile 64 cols
    const int m0 = blockIdx.y * BM;
    const int n0 = blockIdx.x * BN;

    const char* gA = reinterpret_cast<const char*>(g_xh)
                   + (size_t)blockIdx.y * KT64 * A_BYTES;
    const char* gB = reinterpret_cast<const char*>(g_weffh)
                   + (size_t)blockIdx.x * KT64 * B_BYTES;

    if (tid == 0) {
        #pragma unroll
        for (int s = 0; s < STAGES; s++) MBARRIER_INIT(barB + s * 8, 1);
    }
    __syncthreads();

    auto issue = [&](int kt, int st) {
        uint32_t b  = barB + (uint32_t)(st * 8);
        uint32_t so = stg0 + (uint32_t)st * STAGE_BYTES;
        MBARRIER_EXPECT_TX(b, STAGE_BYTES);
        bulkcp(so,           gA + (size_t)kt * A_BYTES, A_BYTES, b);
        bulkcp(so + A_BYTES, gB + (size_t)kt * B_BYTES, B_BYTES, b);
    };
    if (tid == 0) { issue(0, 0); issue(1, 1); }

    // ---- ldmatrix per-lane addressing ----
    const int lr = lane & 7;
    const int g1 = (lane >> 3) & 1;
    const int g2 = lane >> 4;
    const uint32_t aOff = (uint32_t)(wm * 32 + lr + (g1 << 3)) * 128;
    const uint32_t bOff = (uint32_t)(wn * 64 + lr + (g2 << 3)) * 128;

    float acc[2][8][4];
    #pragma unroll
    for (int i = 0; i < 2; i++)
        #pragma unroll
        for (int j = 0; j < 8; j++)
            #pragma unroll
            for (int c = 0; c < 4; c++) acc[i][j][c] = 0.f;

    int st = 0, phase = 0;        // stage/parity cursor for the wait
    int wst = 2;                  // stage to write next (issue distance 2)
    for (int kt = 0; kt < KTILES; kt++) {
        MBARRIER_WAIT_PARITY(barB + st * 8, phase);
        __syncthreads();
        // safe now: stage wst's readers (iteration kt-1) sealed by the sync
        if (tid == 0 && kt + 2 < KTILES) issue(kt + 2, wst);
        if (++wst == STAGES) wst = 0;

        const uint32_t aSt = stg0 + (uint32_t)st * STAGE_BYTES + aOff;
        const uint32_t bSt = stg0 + (uint32_t)st * STAGE_BYTES + A_BYTES + bOff;

        #pragma unroll
        for (int s = 0; s < 4; s++) {          // 4 k-steps of k16
            uint32_t a[2][4], b[4][4];
            const uint32_t xA = (uint32_t)(((2 * s + g2) ^ lr) << 4);
            const uint32_t xB = (uint32_t)(((2 * s + g1) ^ lr) << 4);
            #pragma unroll
            for (int mt = 0; mt < 2; mt++) ldsm4(a[mt], aSt + mt * 2048 + xA);
            #pragma unroll
            for (int p = 0; p < 4; p++)    ldsm4(b[p], bSt + p * 2048 + xB);
            #pragma unroll
            for (int mt = 0; mt < 2; mt++) {
                #pragma unroll
                for (int p = 0; p < 4; p++) {
                    mma16(acc[mt][2 * p],     a[mt], b[p][0], b[p][1]);
                    mma16(acc[mt][2 * p + 1], a[mt], b[p][2], b[p][3]);
                }
            }
        }
        if (++st == STAGES) { st = 0; phase ^= 1; }
    }

    // ---- epilogue: add bias, store float2 ----
    const int mrow = m0 + wm * 32 + (lane >> 2);
    const int ncol = n0 + wn * 64 + 2 * (lane & 3);
    float2 bv[8];
    #pragma unroll
    for (int nt = 0; nt < 8; nt++)
        bv[nt] = *reinterpret_cast<const float2*>(bias + ncol + nt * 8);

    #pragma unroll
    for (int mt = 0; mt < 2; mt++) {
        float* r0 = out + (size_t)(mrow + mt * 16) * NDIM + ncol;
        float* r1 = out + (size_t)(mrow + mt * 16 + 8) * NDIM + ncol;
        #pragma unroll
        for (int nt = 0; nt < 8; nt++) {
            float2 v0 = make_float2(acc[mt][nt][0] + bv[nt].x, acc[mt][nt][1] + bv[nt].y);
            float2 v1 = make_float2(acc[mt][nt][2] + bv[nt].x, acc[mt][nt][3] + bv[nt].y);
            *reinterpret_cast<float2*>(r0 + nt * 8) = v0;
            *reinterpret_cast<float2*>(r1 + nt * 8) = v1;
        }
    }
}

// ---------------- launch ----------------------------------------------------
extern "C" void kernel_launch(void* const* d_in, const int* in_sizes, int n_in,
                              void* d_out, int out_size) {
    const float* x    = (const float*)d_in[0];
    const int*   qw   = (const int*)d_in[1];
    const float* ws   = (const float*)d_in[2];
    const float* pd   = (const float*)d_in[3];
    const float* pu   = (const float*)d_in[4];
    const float* wt   = (const float*)d_in[5];
    const float* bias = (const float*)d_in[6];
    float* out = (float*)d_out;

    // x -> fp16 (RN) into tiled/swizzled g_xh
    round_x_kernel<<<(MDIM * KDIM / 4) / 256, 256>>>((const float4*)x);
    // W_eff = dequant + lora, fp16, tiled/swizzled
    prep_weight_kernel<<<dim3(KDIM / 512, NDIM / 16), 256>>>(qw, ws, pd, pu, wt);

    // main GEMM
    cudaFuncSetAttribute(gemm_fp16_kernel, cudaFuncAttributeMaxDynamicSharedMemorySize, SMEM_TOTAL);
    gemm_fp16_kernel<<<dim3(NDIM / BN, MDIM / BM), 256, SMEM_TOTAL>>>(bias, out);
}

// round 12
// speedup vs baseline: 2.3793x; 1.0435x over previous
#include <cuda_runtime.h>
#include <cuda_fp16.h>
#include <cstdint>

// Problem dims (fixed by the dataset)
#define MDIM 8192
#define KDIM 4096
#define NDIM 4096
#define KT64 (KDIM / 64)   // 64 k-tiles of 64 halves

// ---------------- device scratch (sanctioned: __device__ globals) ----------
// TILE-MAJOR, PRE-SWIZZLED:
//   g_xh    : [m-block(128)][ktile][row 0..127][128B swizzled row]   (64 MB)
//   g_weffh : [n-block(128)][ktile][row 0..127][128B swizzled row]   (32 MB)
__device__ __half g_weffh[(size_t)NDIM * KDIM];
__device__ __half g_xh[(size_t)MDIM * KDIM];

// ---------------- helpers ---------------------------------------------------
__device__ __forceinline__ uint32_t h2_as_u32(__half2 h) {
    return *reinterpret_cast<uint32_t*>(&h);
}
__device__ __forceinline__ uint32_t smem_u32(const void* p) {
    uint32_t a;
    asm("{ .reg .u64 t; cvta.to.shared.u64 t, %1; cvt.u32.u64 %0, t; }" : "=r"(a) : "l"(p));
    return a;
}
__device__ __forceinline__ void ldsm4(uint32_t r[4], uint32_t addr) {
    asm volatile("ldmatrix.sync.aligned.m8n8.x4.shared.b16 {%0,%1,%2,%3}, [%4];"
                 : "=r"(r[0]), "=r"(r[1]), "=r"(r[2]), "=r"(r[3]) : "r"(addr));
}
__device__ __forceinline__ void mma16(float c[4], const uint32_t a[4],
                                      uint32_t b0, uint32_t b1) {
    asm volatile("mma.sync.aligned.m16n8k16.row.col.f32.f16.f16.f32 "
                 "{%0,%1,%2,%3}, {%4,%5,%6,%7}, {%8,%9}, {%0,%1,%2,%3};"
                 : "+f"(c[0]), "+f"(c[1]), "+f"(c[2]), "+f"(c[3])
                 : "r"(a[0]), "r"(a[1]), "r"(a[2]), "r"(a[3]), "r"(b0), "r"(b1));
}
__device__ __forceinline__ void bulkcp(uint32_t dst, const void* src,
                                       uint32_t bytes, uint32_t bar) {
    asm volatile(
        "cp.async.bulk.shared::cta.global.mbarrier::complete_tx::bytes "
        "[%0], [%1], %2, [%3];"
        :: "r"(dst), "l"(src), "r"(bytes), "r"(bar) : "memory");
}
#define MBARRIER_INIT(addr, count) \
    asm volatile("mbarrier.init.shared.b64 [%0], %1;" \
        :: "r"((uint32_t)(addr)), "r"((uint32_t)(count)) : "memory")
#define MBARRIER_EXPECT_TX(addr, bytes) \
    asm volatile("mbarrier.arrive.expect_tx.shared.b64 _, [%0], %1;" \
        :: "r"((uint32_t)(addr)), "r"((uint32_t)(bytes)) : "memory")
#define MBARRIER_WAIT_PARITY(mbar_smem_addr, phase_parity) do { \
    uint32_t _mbar = (uint32_t)(mbar_smem_addr); \
    uint32_t _parity = (uint32_t)(phase_parity); \
    uint32_t _done; \
    asm volatile("{\n\t.reg .pred p;\n\t" \
        "mbarrier.try_wait.parity.acquire.cta.shared::cta.b64 p, [%1], %2;\n\t" \
        "selp.b32 %0, 1, 0, p;\n\t}" \
        : "=r"(_done) : "r"(_mbar), "r"(_parity) : "memory"); \
    if (!_done) { \
        asm volatile("{\n\t.reg .pred P1;\n\t" \
            "WAIT_LOOP_%=:\n\t" \
            "mbarrier.try_wait.parity.acquire.cta.shared::cta.b64 P1, [%0], %1, 0x989680;\n\t" \
            "@P1 bra.uni WAIT_DONE_%=;\n\t" \
            "bra.uni WAIT_LOOP_%=;\n\t" \
            "WAIT_DONE_%=:\n\t}" \
            :: "r"(_mbar), "r"(_parity) : "memory"); \
    } \
} while (0)

// ---------------- kernel 1: round x to fp16, tiled+swizzled (128-row blocks)
__global__ void __launch_bounds__(256) round_x_kernel(const float4* __restrict__ x) {
    int i = blockIdx.x * 256 + threadIdx.x;       // float4 index over [M,K]
    float4 v = x[i];
    int m = i >> 10;                               // K/4 = 1024 float4 per row
    int k = (i & 1023) * 4;
    int mb = m >> 7, row = m & 127;
    int ktile = k >> 6;
    int c = (k >> 3) & 7;
    size_t off = (((size_t)(mb * KT64 + ktile)) * 128 + row) * 128
               + (uint32_t)((c ^ (row & 7)) << 4) + (k & 7) * 2;
    uint2 w;
    w.x = h2_as_u32(__floats2half2_rn(v.x, v.y));
    w.y = h2_as_u32(__floats2half2_rn(v.z, v.w));
    *reinterpret_cast<uint2*>(reinterpret_cast<char*>(g_xh) + off) = w;
}

// ---------------- kernel 2: W_eff = dequant + lora, tiled+swizzled ----------
__global__ void __launch_bounds__(256) prep_weight_kernel(
    const int* __restrict__ qweight, const float* __restrict__ wscales,
    const float* __restrict__ proj_down, const float* __restrict__ proj_up,
    const float* __restrict__ wtscale)
{
    __shared__ float up_s[16 * 32];
    const int n0 = blockIdx.y * 16;
    const int tid = threadIdx.x;
    #pragma unroll
    for (int j = tid; j < 512; j += 256) {
        int n = j >> 5, r = j & 31;
        up_s[j] = proj_up[(size_t)(n0 + n) * 32 + r];
    }
    __syncthreads();
    const float wt = wtscale[0];
    const int k2 = blockIdx.x * 256 + tid;   // pair index; k = 2*k2, 2*k2+1

    float ae[16], ao[16];
    #pragma unroll
    for (int n = 0; n < 16; n++) { ae[n] = 0.f; ao[n] = 0.f; }
    #pragma unroll 4
    for (int r = 0; r < 32; r++) {
        float2 d2 = *reinterpret_cast<const float2*>(proj_down + (size_t)r * KDIM + 2 * k2);
        #pragma unroll
        for (int n = 0; n < 16; n++) {
            float u = up_s[n * 32 + r];
            ae[n] = fmaf(u, d2.x, ae[n]);
            ao[n] = fmaf(u, d2.y, ao[n]);
        }
    }
    const int g = k2 >> 5;
    const int k = 2 * k2;
    const int ktile = k >> 6;
    const int c = (k >> 3) & 7;
    #pragma unroll
    for (int nn = 0; nn < 16; nn++) {
        int n = n0 + nn;
        int q = qweight[(size_t)n * (KDIM / 2) + k2];
        float s = wscales[(size_t)g * NDIM + n];
        float we = fmaf((float)((q & 15) - 8), s, wt * ae[nn]);
        float wo = fmaf((float)(((q >> 4) & 15) - 8), s, wt * ao[nn]);
        int nb = n >> 7, rowb = n & 127;
        size_t off = (((size_t)(nb * KT64 + ktile)) * 128 + rowb) * 128
                   + (uint32_t)((c ^ (rowb & 7)) << 4) + (k & 7) * 2;
        __half2 hv = __floats2half2_rn(we, wo);
        *reinterpret_cast<__half2*>(reinterpret_cast<char*>(g_weffh) + off) = hv;
    }
}

// ---------------- GEMM: 128x128 tile, 128 thr (64x64 warp tiles), ----------
// 2 CTAs/SM, bulk-fed, fragment double-buffered (R4 schedule).
// smem traffic/ktile: reads 2xA + 2xB = 64KB + 32KB write = 96KB -> 768 cyc
// vs 1024 tensor cyc: tensor pipe becomes the sole binder.
#define BM 128
#define BN 128
#define BK 64
#define STAGES 3
#define KTILES KT64                       // 64
#define A_BYTES (BM * BK * 2)             // 16384
#define B_BYTES (BN * BK * 2)             // 16384
#define STAGE_BYTES (A_BYTES + B_BYTES)   // 32768
#define OFF_BAR   0
#define OFF_STAGE 1024
#define SMEM_TOTAL (OFF_STAGE + STAGES * STAGE_BYTES)   // 99328 -> 2 CTAs/SM

__global__ void __launch_bounds__(128, 2) gemm_fp16_kernel(
    const float* __restrict__ bias, float* __restrict__ out)
{
    extern __shared__ char smem_raw[];
    const uint32_t sbase = smem_u32(smem_raw);
    const uint32_t barB  = sbase + OFF_BAR;
    const uint32_t stg0  = sbase + OFF_STAGE;

    const int tid  = threadIdx.x;
    const int lane = tid & 31;
    const int warp = tid >> 5;
    const int wm = warp & 1;          // 2 warps in m -> warp tile 64 rows
    const int wn = warp >> 1;         // 2 warps in n -> warp tile 64 cols
    const int m0 = blockIdx.y * BM;
    const int n0 = blockIdx.x * BN;

    const char* gA = reinterpret_cast<const char*>(g_xh)
                   + (size_t)blockIdx.y * KT64 * A_BYTES;
    const char* gB = reinterpret_cast<const char*>(g_weffh)
                   + (size_t)blockIdx.x * KT64 * B_BYTES;

    if (tid == 0) {
        #pragma unroll
        for (int s = 0; s < STAGES; s++) MBARRIER_INIT(barB + s * 8, 1);
    }
    __syncthreads();

    auto issue = [&](int kt, int stg) {
        uint32_t b  = barB + (uint32_t)(stg * 8);
        uint32_t so = stg0 + (uint32_t)stg * STAGE_BYTES;
        MBARRIER_EXPECT_TX(b, STAGE_BYTES);
        bulkcp(so,           gA + (size_t)kt * A_BYTES, A_BYTES, b);
        bulkcp(so + A_BYTES, gB + (size_t)kt * B_BYTES, B_BYTES, b);
    };
    if (tid == 0) { issue(0, 0); issue(1, 1); }

    // ---- ldmatrix per-lane addressing (R4 geometry) ----
    const int lr = lane & 7;
    const int g1 = (lane >> 3) & 1;
    const int g2 = lane >> 4;
    const uint32_t aOff = (uint32_t)(wm * 64 + lr + (g1 << 3)) * 128;
    const uint32_t bOff = (uint32_t)(wn * 64 + lr + (g2 << 3)) * 128;

    float acc[4][8][4];
    #pragma unroll
    for (int i = 0; i < 4; i++)
        #pragma unroll
        for (int j = 0; j < 8; j++)
            #pragma unroll
            for (int c = 0; c < 4; c++) acc[i][j][c] = 0.f;

    // fragment double buffers (R4 schedule)
    uint32_t fa[2][4][4], fb[2][4][4];
    auto ldsm_step = [&](int buf, int stg, int s) {
        const uint32_t aSt = stg0 + (uint32_t)stg * STAGE_BYTES + aOff;
        const uint32_t bSt = stg0 + (uint32_t)stg * STAGE_BYTES + A_BYTES + bOff;
        const uint32_t xA = (uint32_t)(((2 * s + g2) ^ lr) << 4);
        const uint32_t xB = (uint32_t)(((2 * s + g1) ^ lr) << 4);
        #pragma unroll
        for (int mt = 0; mt < 4; mt++) {
            ldsm4(fa[buf][mt], aSt + mt * 2048 + xA);
            ldsm4(fb[buf][mt], bSt + mt * 2048 + xB);
        }
    };
    auto mma_step = [&](int buf) {
        #pragma unroll
        for (int mt = 0; mt < 4; mt++) {
            #pragma unroll
            for (int p = 0; p < 4; p++) {
                mma16(acc[mt][2 * p],     fa[buf][mt], fb[buf][p][0], fb[buf][p][1]);
                mma16(acc[mt][2 * p + 1], fa[buf][mt], fb[buf][p][2], fb[buf][p][3]);
            }
        }
    };

    int st = 0, phase = 0;        // read cursor
    int wst = 2;                  // write cursor (issue distance 2)
    for (int kt = 0; kt < KTILES; kt++) {
        MBARRIER_WAIT_PARITY(barB + st * 8, phase);
        __syncthreads();
        // stage wst's last readers (iteration kt-1) sealed by the sync above
        if (tid == 0 && kt + 2 < KTILES) issue(kt + 2, wst);
        if (++wst == STAGES) wst = 0;

        ldsm_step(0, st, 0);
        #pragma unroll
        for (int s = 0; s < 4; s++) {
            const int cur = s & 1;
            if (s < 3) {
                ldsm_step(cur ^ 1, st, s + 1);   // prefetch next step's fragments
                mma_step(cur);
            } else {
                mma_step(cur);                    // last MMAs cover next wait
            }
        }
        if (++st == STAGES) { st = 0; phase ^= 1; }
    }

    // ---- epilogue: add bias, store float2 ----
    const int mrow = m0 + wm * 64 + (lane >> 2);
    const int ncol = n0 + wn * 64 + 2 * (lane & 3);
    float2 bv[8];
    #pragma unroll
    for (int nt = 0; nt < 8; nt++)
        bv[nt] = *reinterpret_cast<const float2*>(bias + ncol + nt * 8);

    #pragma unroll
    for (int mt = 0; mt < 4; mt++) {
        float* r0 = out + (size_t)(mrow + mt * 16) * NDIM + ncol;
        float* r1 = out + (size_t)(mrow + mt * 16 + 8) * NDIM + ncol;
        #pragma unroll
        for (int nt = 0; nt < 8; nt++) {
            float2 v0 = make_float2(acc[mt][nt][0] + bv[nt].x, acc[mt][nt][1] + bv[nt].y);
            float2 v1 = make_float2(acc[mt][nt][2] + bv[nt].x, acc[mt][nt][3] + bv[nt].y);
            *reinterpret_cast<float2*>(r0 + nt * 8) = v0;
            *reinterpret_cast<float2*>(r1 + nt * 8) = v1;
        }
    }
}

// ---------------- launch ----------------------------------------------------
extern "C" void kernel_launch(void* const* d_in, const int* in_sizes, int n_in,
                              void* d_out, int out_size) {
    const float* x    = (const float*)d_in[0];
    const int*   qw   = (const int*)d_in[1];
    const float* ws   = (const float*)d_in[2];
    const float* pd   = (const float*)d_in[3];
    const float* pu   = (const float*)d_in[4];
    const float* wt   = (const float*)d_in[5];
    const float* bias = (const float*)d_in[6];
    float* out = (float*)d_out;

    // x -> fp16 (RN) into tiled/swizzled g_xh
    round_x_kernel<<<(MDIM * KDIM / 4) / 256, 256>>>((const float4*)x);
    // W_eff = dequant + lora, fp16, tiled/swizzled
    prep_weight_kernel<<<dim3(KDIM / 512, NDIM / 16), 256>>>(qw, ws, pd, pu, wt);

    // main GEMM
    cudaFuncSetAttribute(gemm_fp16_kernel, cudaFuncAttributeMaxDynamicSharedMemorySize, SMEM_TOTAL);
    gemm_fp16_kernel<<<dim3(NDIM / BN, MDIM / BM), 128, SMEM_TOTAL>>>(bias, out);
}

// round 13
// speedup vs baseline: 2.4483x; 1.0290x over previous
#include <cuda_runtime.h>
#include <cuda_fp16.h>
#include <cstdint>

// Problem dims (fixed by the dataset)
#define MDIM 8192
#define KDIM 4096
#define NDIM 4096
#define KT64 (KDIM / 64)   // 64 k-tiles of 64 halves

// ---------------- device scratch (sanctioned: __device__ globals) ----------
// TILE-MAJOR, PRE-SWIZZLED:
//   g_xh    : [m-block(128)][ktile][row 0..127][128B swizzled row]   (64 MB)
//   g_weffh : [n-block(128)][ktile][row 0..127][128B swizzled row]   (32 MB)
__device__ __half g_weffh[(size_t)NDIM * KDIM];
__device__ __half g_xh[(size_t)MDIM * KDIM];

// ---------------- helpers ---------------------------------------------------
__device__ __forceinline__ uint32_t h2_as_u32(__half2 h) {
    return *reinterpret_cast<uint32_t*>(&h);
}
__device__ __forceinline__ uint32_t smem_u32(const void* p) {
    uint32_t a;
    asm("{ .reg .u64 t; cvta.to.shared.u64 t, %1; cvt.u32.u64 %0, t; }" : "=r"(a) : "l"(p));
    return a;
}
__device__ __forceinline__ void ldsm4(uint32_t r[4], uint32_t addr) {
    asm volatile("ldmatrix.sync.aligned.m8n8.x4.shared.b16 {%0,%1,%2,%3}, [%4];"
                 : "=r"(r[0]), "=r"(r[1]), "=r"(r[2]), "=r"(r[3]) : "r"(addr));
}
__device__ __forceinline__ void mma16(float c[4], const uint32_t a[4],
                                      uint32_t b0, uint32_t b1) {
    asm volatile("mma.sync.aligned.m16n8k16.row.col.f32.f16.f16.f32 "
                 "{%0,%1,%2,%3}, {%4,%5,%6,%7}, {%8,%9}, {%0,%1,%2,%3};"
                 : "+f"(c[0]), "+f"(c[1]), "+f"(c[2]), "+f"(c[3])
                 : "r"(a[0]), "r"(a[1]), "r"(a[2]), "r"(a[3]), "r"(b0), "r"(b1));
}
__device__ __forceinline__ void bulkcp(uint32_t dst, const void* src,
                                       uint32_t bytes, uint32_t bar) {
    asm volatile(
        "cp.async.bulk.shared::cta.global.mbarrier::complete_tx::bytes "
        "[%0], [%1], %2, [%3];"
        :: "r"(dst), "l"(src), "r"(bytes), "r"(bar) : "memory");
}
#define MBARRIER_INIT(addr, count) \
    asm volatile("mbarrier.init.shared.b64 [%0], %1;" \
        :: "r"((uint32_t)(addr)), "r"((uint32_t)(count)) : "memory")
#define MBARRIER_EXPECT_TX(addr, bytes) \
    asm volatile("mbarrier.arrive.expect_tx.shared.b64 _, [%0], %1;" \
        :: "r"((uint32_t)(addr)), "r"((uint32_t)(bytes)) : "memory")
#define MBARRIER_ARRIVE(addr) \
    asm volatile("mbarrier.arrive.shared.b64 _, [%0];" \
        :: "r"((uint32_t)(addr)) : "memory")
#define MBARRIER_WAIT_PARITY(mbar_smem_addr, phase_parity) do { \
    uint32_t _mbar = (uint32_t)(mbar_smem_addr); \
    uint32_t _parity = (uint32_t)(phase_parity); \
    uint32_t _done; \
    asm volatile("{\n\t.reg .pred p;\n\t" \
        "mbarrier.try_wait.parity.acquire.cta.shared::cta.b64 p, [%1], %2;\n\t" \
        "selp.b32 %0, 1, 0, p;\n\t}" \
        : "=r"(_done) : "r"(_mbar), "r"(_parity) : "memory"); \
    if (!_done) { \
        asm volatile("{\n\t.reg .pred P1;\n\t" \
            "WAIT_LOOP_%=:\n\t" \
            "mbarrier.try_wait.parity.acquire.cta.shared::cta.b64 P1, [%0], %1, 0x989680;\n\t" \
            "@P1 bra.uni WAIT_DONE_%=;\n\t" \
            "bra.uni WAIT_LOOP_%=;\n\t" \
            "WAIT_DONE_%=:\n\t}" \
            :: "r"(_mbar), "r"(_parity) : "memory"); \
    } \
} while (0)

// ---------------- kernel 1: round x to fp16, tiled+swizzled (128-row blocks)
__global__ void __launch_bounds__(256) round_x_kernel(const float4* __restrict__ x) {
    int i = blockIdx.x * 256 + threadIdx.x;       // float4 index over [M,K]
    float4 v = x[i];
    int m = i >> 10;                               // K/4 = 1024 float4 per row
    int k = (i & 1023) * 4;
    int mb = m >> 7, row = m & 127;
    int ktile = k >> 6;
    int c = (k >> 3) & 7;
    size_t off = (((size_t)(mb * KT64 + ktile)) * 128 + row) * 128
               + (uint32_t)((c ^ (row & 7)) << 4) + (k & 7) * 2;
    uint2 w;
    w.x = h2_as_u32(__floats2half2_rn(v.x, v.y));
    w.y = h2_as_u32(__floats2half2_rn(v.z, v.w));
    *reinterpret_cast<uint2*>(reinterpret_cast<char*>(g_xh) + off) = w;
}

// ---------------- kernel 2: W_eff = dequant + lora, tiled+swizzled ----------
__global__ void __launch_bounds__(256) prep_weight_kernel(
    const int* __restrict__ qweight, const float* __restrict__ wscales,
    const float* __restrict__ proj_down, const float* __restrict__ proj_up,
    const float* __restrict__ wtscale)
{
    __shared__ float up_s[16 * 32];
    const int n0 = blockIdx.y * 16;
    const int tid = threadIdx.x;
    #pragma unroll
    for (int j = tid; j < 512; j += 256) {
        int n = j >> 5, r = j & 31;
        up_s[j] = proj_up[(size_t)(n0 + n) * 32 + r];
    }
    __syncthreads();
    const float wt = wtscale[0];
    const int k2 = blockIdx.x * 256 + tid;   // pair index; k = 2*k2, 2*k2+1

    float ae[16], ao[16];
    #pragma unroll
    for (int n = 0; n < 16; n++) { ae[n] = 0.f; ao[n] = 0.f; }
    #pragma unroll 4
    for (int r = 0; r < 32; r++) {
        float2 d2 = *reinterpret_cast<const float2*>(proj_down + (size_t)r * KDIM + 2 * k2);
        #pragma unroll
        for (int n = 0; n < 16; n++) {
            float u = up_s[n * 32 + r];
            ae[n] = fmaf(u, d2.x, ae[n]);
            ao[n] = fmaf(u, d2.y, ao[n]);
        }
    }
    const int g = k2 >> 5;
    const int k = 2 * k2;
    const int ktile = k >> 6;
    const int c = (k >> 3) & 7;
    #pragma unroll
    for (int nn = 0; nn < 16; nn++) {
        int n = n0 + nn;
        int q = qweight[(size_t)n * (KDIM / 2) + k2];
        float s = wscales[(size_t)g * NDIM + n];
        float we = fmaf((float)((q & 15) - 8), s, wt * ae[nn]);
        float wo = fmaf((float)(((q >> 4) & 15) - 8), s, wt * ao[nn]);
        int nb = n >> 7, rowb = n & 127;
        size_t off = (((size_t)(nb * KT64 + ktile)) * 128 + rowb) * 128
                   + (uint32_t)((c ^ (rowb & 7)) << 4) + (k & 7) * 2;
        __half2 hv = __floats2half2_rn(we, wo);
        *reinterpret_cast<__half2*>(reinterpret_cast<char*>(g_weffh) + off) = hv;
    }
}

// ---------------- GEMM: 128x128 tile, 64x64 warp tiles, 2 CTAs/SM, ---------
// bulk-fed, fragment double-buffered, full/empty mbarrier ring — NO
// per-ktile __syncthreads (block-wide drains replaced by per-warp
// empty-arrivals; only the producer thread ever waits for WAR safety).
#define BM 128
#define BN 128
#define BK 64
#define STAGES 3
#define KTILES KT64                       // 64
#define A_BYTES (BM * BK * 2)             // 16384
#define B_BYTES (BN * BK * 2)             // 16384
#define STAGE_BYTES (A_BYTES + B_BYTES)   // 32768
#define OFF_FULL  0                       // 3 x 8B
#define OFF_EMPTY 24                      // 3 x 8B
#define OFF_STAGE 1024
#define SMEM_TOTAL (OFF_STAGE + STAGES * STAGE_BYTES)   // 99328 -> 2 CTAs/SM

__global__ void __launch_bounds__(128, 2) gemm_fp16_kernel(
    const float* __restrict__ bias, float* __restrict__ out)
{
    extern __shared__ char smem_raw[];
    const uint32_t sbase = smem_u32(smem_raw);
    const uint32_t fullB  = sbase + OFF_FULL;
    const uint32_t emptyB = sbase + OFF_EMPTY;
    const uint32_t stg0   = sbase + OFF_STAGE;

    const int tid  = threadIdx.x;
    const int lane = tid & 31;
    const int warp = tid >> 5;
    const int wm = warp & 1;          // 2 warps in m -> warp tile 64 rows
    const int wn = warp >> 1;         // 2 warps in n -> warp tile 64 cols
    const int m0 = blockIdx.y * BM;
    const int n0 = blockIdx.x * BN;

    const char* gA = reinterpret_cast<const char*>(g_xh)
                   + (size_t)blockIdx.y * KT64 * A_BYTES;
    const char* gB = reinterpret_cast<const char*>(g_weffh)
                   + (size_t)blockIdx.x * KT64 * B_BYTES;

    if (tid == 0) {
        #pragma unroll
        for (int s = 0; s < STAGES; s++) {
            MBARRIER_INIT(fullB  + s * 8, 1);
            MBARRIER_INIT(emptyB + s * 8, 4);   // one arrival per warp
        }
    }
    __syncthreads();   // init visibility (only block-wide sync in the kernel)

    auto issue = [&](int kt, int stg) {
        uint32_t b  = fullB + (uint32_t)(stg * 8);
        uint32_t so = stg0 + (uint32_t)stg * STAGE_BYTES;
        MBARRIER_EXPECT_TX(b, STAGE_BYTES);
        bulkcp(so,           gA + (size_t)kt * A_BYTES, A_BYTES, b);
        bulkcp(so + A_BYTES, gB + (size_t)kt * B_BYTES, B_BYTES, b);
    };
    if (tid == 0) { issue(0, 0); issue(1, 1); }

    // ---- ldmatrix per-lane addressing (R4 geometry) ----
    const int lr = lane & 7;
    const int g1 = (lane >> 3) & 1;
    const int g2 = lane >> 4;
    const uint32_t aOff = (uint32_t)(wm * 64 + lr + (g1 << 3)) * 128;
    const uint32_t bOff = (uint32_t)(wn * 64 + lr + (g2 << 3)) * 128;

    float acc[4][8][4];
    #pragma unroll
    for (int i = 0; i < 4; i++)
        #pragma unroll
        for (int j = 0; j < 8; j++)
            #pragma unroll
            for (int c = 0; c < 4; c++) acc[i][j][c] = 0.f;

    // fragment double buffers (R4 schedule)
    uint32_t fa[2][4][4], fb[2][4][4];
    auto ldsm_step = [&](int buf, int stg, int s) {
        const uint32_t aSt = stg0 + (uint32_t)stg * STAGE_BYTES + aOff;
        const uint32_t bSt = stg0 + (uint32_t)stg * STAGE_BYTES + A_BYTES + bOff;
        const uint32_t xA = (uint32_t)(((2 * s + g2) ^ lr) << 4);
        const uint32_t xB = (uint32_t)(((2 * s + g1) ^ lr) << 4);
        #pragma unroll
        for (int mt = 0; mt < 4; mt++) {
            ldsm4(fa[buf][mt], aSt + mt * 2048 + xA);
            ldsm4(fb[buf][mt], bSt + mt * 2048 + xB);
        }
    };
    auto mma_step = [&](int buf) {
        #pragma unroll
        for (int mt = 0; mt < 4; mt++) {
            #pragma unroll
            for (int p = 0; p < 4; p++) {
                mma16(acc[mt][2 * p],     fa[buf][mt], fb[buf][p][0], fb[buf][p][1]);
                mma16(acc[mt][2 * p + 1], fa[buf][mt], fb[buf][p][2], fb[buf][p][3]);
            }
        }
    };

    int st = 0, phase = 0;        // read cursor (full bars)
    int wst = 2;                  // write cursor (issue distance 2)
    for (int kt = 0; kt < KTILES; kt++) {
        // -------- producer: WAR-wait on empty, then re-issue --------
        if (tid == 0 && kt + 2 < KTILES) {
            if (kt >= 1) {
                // stage wst's j-th reuse: j = (kt-1)/3; completed read-groups
                // parity = j & 1
                int epar = ((kt - 1) / 3) & 1;
                MBARRIER_WAIT_PARITY(emptyB + wst * 8, epar);
            }
            issue(kt + 2, wst);
        }
        if (++wst == STAGES) wst = 0;

        // -------- consumers: wait data, compute, release stage --------
        MBARRIER_WAIT_PARITY(fullB + st * 8, phase);

        ldsm_step(0, st, 0);
        #pragma unroll
        for (int s = 0; s < 4; s++) {
            const int cur = s & 1;
            if (s < 3) {
                ldsm_step(cur ^ 1, st, s + 1);   // prefetch next step's fragments
                mma_step(cur);
            } else {
                mma_step(cur);                    // last MMAs cover next wait
            }
        }
        // all of this warp's reads of stage st are complete (ldmatrix is
        // warp-synchronous) -> lane 0 releases the stage
        if (lane == 0) MBARRIER_ARRIVE(emptyB + st * 8);

        if (++st == STAGES) { st = 0; phase ^= 1; }
    }

    // ---- epilogue: add bias, store float2 ----
    const int mrow = m0 + wm * 64 + (lane >> 2);
    const int ncol = n0 + wn * 64 + 2 * (lane & 3);
    float2 bv[8];
    #pragma unroll
    for (int nt = 0; nt < 8; nt++)
        bv[nt] = *reinterpret_cast<const float2*>(bias + ncol + nt * 8);

    #pragma unroll
    for (int mt = 0; mt < 4; mt++) {
        float* r0 = out + (size_t)(mrow + mt * 16) * NDIM + ncol;
        float* r1 = out + (size_t)(mrow + mt * 16 + 8) * NDIM + ncol;
        #pragma unroll
        for (int nt = 0; nt < 8; nt++) {
            float2 v0 = make_float2(acc[mt][nt][0] + bv[nt].x, acc[mt][nt][1] + bv[nt].y);
            float2 v1 = make_float2(acc[mt][nt][2] + bv[nt].x, acc[mt][nt][3] + bv[nt].y);
            *reinterpret_cast<float2*>(r0 + nt * 8) = v0;
            *reinterpret_cast<float2*>(r1 + nt * 8) = v1;
        }
    }
}

// ---------------- launch ----------------------------------------------------
extern "C" void kernel_launch(void* const* d_in, const int* in_sizes, int n_in,
                              void* d_out, int out_size) {
    const float* x    = (const float*)d_in[0];
    const int*   qw   = (const int*)d_in[1];
    const float* ws   = (const float*)d_in[2];
    const float* pd   = (const float*)d_in[3];
    const float* pu   = (const float*)d_in[4];
    const float* wt   = (const float*)d_in[5];
    const float* bias = (const float*)d_in[6];
    float* out = (float*)d_out;

    // x -> fp16 (RN) into tiled/swizzled g_xh
    round_x_kernel<<<(MDIM * KDIM / 4) / 256, 256>>>((const float4*)x);
    // W_eff = dequant + lora, fp16, tiled/swizzled
    prep_weight_kernel<<<dim3(KDIM / 512, NDIM / 16), 256>>>(qw, ws, pd, pu, wt);

    // main GEMM
    cudaFuncSetAttribute(gemm_fp16_kernel, cudaFuncAttributeMaxDynamicSharedMemorySize, SMEM_TOTAL);
    gemm_fp16_kernel<<<dim3(NDIM / BN, MDIM / BM), 128, SMEM_TOTAL>>>(bias, out);
}